// round 1
// baseline (speedup 1.0000x reference)
#include <cuda_runtime.h>
#include <math.h>
#include <stdint.h>

// Problem constants
#define SEQ   4096
#define DMODEL 1024
#define NHEAD 16
#define HDIM  64
#define HALF  32   // HDIM/2

// ---------------- scratch (device globals; no allocation allowed) ----------------
__device__ float g_q[(size_t)NHEAD * SEQ * HDIM];   // [h][t][d]
__device__ float g_k[(size_t)NHEAD * SEQ * HDIM];
__device__ float g_v[(size_t)NHEAD * SEQ * HDIM];
__device__ float g_y[(size_t)SEQ * DMODEL];         // [t][h*64+d]
__device__ float g_cos[SEQ * HALF];
__device__ float g_sin[SEQ * HALF];

// ---------------- RoPE cos/sin table ----------------
// Replicates reference rounding: inv_freq rounded to fp32, freq = fp32(t * inv_freq),
// then accurate (double) cos/sin of that fp32 value.
__global__ void rope_table_kernel() {
    int idx = blockIdx.x * blockDim.x + threadIdx.x;     // SEQ*HALF = 131072
    if (idx >= SEQ * HALF) return;
    int d = idx & (HALF - 1);
    int t = idx >> 5;
    double inv = exp(-log(10000.0) * (double)d / (double)HALF);
    float invf = (float)inv;
    float f = (float)t * invf;                // fp32 product, like jnp.outer in fp32
    g_cos[idx] = (float)cos((double)f);
    g_sin[idx] = (float)sin((double)f);
}

// ---------------- RoPE apply (in-place on g_q, g_k) ----------------
__global__ void rope_apply_kernel() {
    int idx = blockIdx.x * blockDim.x + threadIdx.x;     // NHEAD*SEQ*HALF = 2097152
    if (idx >= NHEAD * SEQ * HALF) return;
    int d = idx & (HALF - 1);
    int t = (idx >> 5) & (SEQ - 1);
    int h = idx >> 17;
    float c = g_cos[t * HALF + d];
    float s = g_sin[t * HALF + d];
    size_t base = ((size_t)h * SEQ + t) * HDIM;
    float q1 = g_q[base + d];
    float q2 = g_q[base + d + HALF];
    g_q[base + d]        = q1 * c - q2 * s;
    g_q[base + d + HALF] = q2 * c + q1 * s;
    float k1 = g_k[base + d];
    float k2 = g_k[base + d + HALF];
    g_k[base + d]        = k1 * c - k2 * s;
    g_k[base + d + HALF] = k2 * c + k1 * s;
}

// ---------------- SGEMM: C = A @ B ----------------
// 128x128 block tile, BK=8, 256 threads, 8x8 micro-tile.
// mode 0: plain write to C.  mode 1: scatter epilogue into g_q/g_k/g_v.
// mode 2: A is ignored; read from g_y; plain write to C.
__global__ __launch_bounds__(256) void sgemm_kernel(
    const float* __restrict__ A, const float* __restrict__ Bm,
    float* __restrict__ C, int M, int N, int K, int mode)
{
    __shared__ float As[8][128];
    __shared__ float Bs[8][128];

    const int tid  = threadIdx.x;
    const int brow = blockIdx.y * 128;
    const int bcol = blockIdx.x * 128;

    const float* __restrict__ Ap = (mode == 2) ? (const float*)g_y : A;

    const int arow   = tid >> 1;            // 0..127
    const int acol   = (tid & 1) << 2;      // 0 or 4
    const int brow_l = tid >> 5;            // 0..7
    const int bcol_l = (tid & 31) << 2;     // 0..124

    const int trow = (tid >> 4) << 3;       // 0..120 step 8
    const int tcol = (tid & 15) << 3;       // 0..120 step 8

    float acc[8][8];
    #pragma unroll
    for (int i = 0; i < 8; i++)
        #pragma unroll
        for (int j = 0; j < 8; j++) acc[i][j] = 0.f;

    for (int k0 = 0; k0 < K; k0 += 8) {
        float4 av = *(const float4*)(Ap + (size_t)(brow + arow) * K + k0 + acol);
        As[acol + 0][arow] = av.x;
        As[acol + 1][arow] = av.y;
        As[acol + 2][arow] = av.z;
        As[acol + 3][arow] = av.w;
        *(float4*)&Bs[brow_l][bcol_l] =
            *(const float4*)(Bm + (size_t)(k0 + brow_l) * N + bcol + bcol_l);
        __syncthreads();

        #pragma unroll
        for (int k = 0; k < 8; k++) {
            float4 a0 = *(const float4*)&As[k][trow];
            float4 a1 = *(const float4*)&As[k][trow + 4];
            float4 b0 = *(const float4*)&Bs[k][tcol];
            float4 b1 = *(const float4*)&Bs[k][tcol + 4];
            float ra[8] = {a0.x, a0.y, a0.z, a0.w, a1.x, a1.y, a1.z, a1.w};
            float rb[8] = {b0.x, b0.y, b0.z, b0.w, b1.x, b1.y, b1.z, b1.w};
            #pragma unroll
            for (int i = 0; i < 8; i++)
                #pragma unroll
                for (int j = 0; j < 8; j++)
                    acc[i][j] += ra[i] * rb[j];
        }
        __syncthreads();
    }

    if (mode == 1) {
        // scatter into g_q / g_k / g_v as [h][t][d]
        #pragma unroll
        for (int i = 0; i < 8; i++) {
            int t = brow + trow + i;
            #pragma unroll
            for (int j = 0; j < 8; j++) {
                int n    = bcol + tcol + j;
                int sect = n >> 10;          // 0:q 1:k 2:v
                int nn   = n & 1023;
                int h    = nn >> 6;
                int d    = nn & 63;
                float* dst = (sect == 0) ? g_q : (sect == 1) ? g_k : g_v;
                dst[((size_t)h * SEQ + t) * HDIM + d] = acc[i][j];
            }
        }
    } else {
        #pragma unroll
        for (int i = 0; i < 8; i++) {
            size_t off = (size_t)(brow + trow + i) * N + bcol + tcol;
            *(float4*)(C + off)     = make_float4(acc[i][0], acc[i][1], acc[i][2], acc[i][3]);
            *(float4*)(C + off + 4) = make_float4(acc[i][4], acc[i][5], acc[i][6], acc[i][7]);
        }
    }
}

// ---------------- Flash attention (fp32, causal) ----------------
// One block per (head, 64-query tile). 128 threads: ty=tid/16 owns 8 rows,
// tx=tid%16 owns 4 cols. P tile aliases the K tile.
#define ATT_PAD 68
__global__ __launch_bounds__(128) void attn_kernel() {
    extern __shared__ float sm[];
    float (*Qs)[ATT_PAD] = (float(*)[ATT_PAD])(sm);
    float (*Ks)[ATT_PAD] = (float(*)[ATT_PAD])(sm + 64 * ATT_PAD);
    float (*Vt)[ATT_PAD] = (float(*)[ATT_PAD])(sm + 2 * 64 * ATT_PAD);

    const int tid = threadIdx.x;
    const int tx  = tid & 15;
    const int ty  = tid >> 4;
    const int h   = blockIdx.y;
    const int qt  = blockIdx.x;
    const int q0  = qt * 64;

    const float* __restrict__ Qh = g_q + (size_t)h * SEQ * HDIM;
    const float* __restrict__ Kh = g_k + (size_t)h * SEQ * HDIM;
    const float* __restrict__ Vh = g_v + (size_t)h * SEQ * HDIM;

    // load Q tile [64][64]
    for (int i = tid; i < 64 * 16; i += 128) {
        int row = i >> 4, c4 = (i & 15) << 2;
        *(float4*)&Qs[row][c4] = *(const float4*)(Qh + (size_t)(q0 + row) * HDIM + c4);
    }

    float m[8], l[8], o[8][4];
    #pragma unroll
    for (int i = 0; i < 8; i++) {
        m[i] = -1e30f; l[i] = 0.f;
        #pragma unroll
        for (int j = 0; j < 4; j++) o[i][j] = 0.f;
    }

    for (int j = 0; j <= qt; j++) {
        __syncthreads();   // prior PV done reading Ks(P)/Vt; Q load covered on iter 0
        // load K tile into Ks[key][d], V tile transposed into Vt[d][key]
        for (int i = tid; i < 64 * 16; i += 128) {
            int row = i >> 4, c4 = (i & 15) << 2;
            size_t g = (size_t)(j * 64 + row) * HDIM + c4;
            *(float4*)&Ks[row][c4] = *(const float4*)(Kh + g);
            float4 vv = *(const float4*)(Vh + g);
            Vt[c4 + 0][row] = vv.x;
            Vt[c4 + 1][row] = vv.y;
            Vt[c4 + 2][row] = vv.z;
            Vt[c4 + 3][row] = vv.w;
        }
        __syncthreads();

        // S = Q K^T
        float s[8][4];
        #pragma unroll
        for (int i = 0; i < 8; i++)
            #pragma unroll
            for (int jj = 0; jj < 4; jj++) s[i][jj] = 0.f;

        #pragma unroll
        for (int kk = 0; kk < 64; kk += 4) {
            float4 kf[4];
            #pragma unroll
            for (int jj = 0; jj < 4; jj++)
                kf[jj] = *(const float4*)&Ks[tx * 4 + jj][kk];
            #pragma unroll
            for (int i = 0; i < 8; i++) {
                float4 qf = *(const float4*)&Qs[ty * 8 + i][kk];
                #pragma unroll
                for (int jj = 0; jj < 4; jj++)
                    s[i][jj] += qf.x * kf[jj].x + qf.y * kf[jj].y
                              + qf.z * kf[jj].z + qf.w * kf[jj].w;
            }
        }

        const bool diag = (j == qt);
        #pragma unroll
        for (int i = 0; i < 8; i++) {
            int qrow = q0 + ty * 8 + i;
            float mx = -1e30f;
            #pragma unroll
            for (int jj = 0; jj < 4; jj++) {
                float v = s[i][jj] * 0.125f;   // 1/sqrt(64)
                if (diag && (j * 64 + tx * 4 + jj) > qrow) v = -1e30f;
                s[i][jj] = v;
                mx = fmaxf(mx, v);
            }
            mx = fmaxf(mx, __shfl_xor_sync(0xffffffffu, mx, 8, 16));
            mx = fmaxf(mx, __shfl_xor_sync(0xffffffffu, mx, 4, 16));
            mx = fmaxf(mx, __shfl_xor_sync(0xffffffffu, mx, 2, 16));
            mx = fmaxf(mx, __shfl_xor_sync(0xffffffffu, mx, 1, 16));
            float mnew = fmaxf(m[i], mx);
            float corr = expf(m[i] - mnew);
            float rs = 0.f;
            #pragma unroll
            for (int jj = 0; jj < 4; jj++) {
                float p = expf(s[i][jj] - mnew);
                s[i][jj] = p;
                rs += p;
            }
            rs += __shfl_xor_sync(0xffffffffu, rs, 8, 16);
            rs += __shfl_xor_sync(0xffffffffu, rs, 4, 16);
            rs += __shfl_xor_sync(0xffffffffu, rs, 2, 16);
            rs += __shfl_xor_sync(0xffffffffu, rs, 1, 16);
            l[i] = l[i] * corr + rs;
            m[i] = mnew;
            #pragma unroll
            for (int jj = 0; jj < 4; jj++) o[i][jj] *= corr;
        }

        __syncthreads();   // all S reads of Ks complete before P overwrite
        #pragma unroll
        for (int i = 0; i < 8; i++)
            #pragma unroll
            for (int jj = 0; jj < 4; jj++)
                Ks[ty * 8 + i][tx * 4 + jj] = s[i][jj];
        __syncthreads();

        // O += P @ V
        #pragma unroll
        for (int kk = 0; kk < 64; kk += 4) {
            float4 vf[4];
            #pragma unroll
            for (int jj = 0; jj < 4; jj++)
                vf[jj] = *(const float4*)&Vt[tx * 4 + jj][kk];
            #pragma unroll
            for (int i = 0; i < 8; i++) {
                float4 pf = *(const float4*)&Ks[ty * 8 + i][kk];
                #pragma unroll
                for (int jj = 0; jj < 4; jj++)
                    o[i][jj] += pf.x * vf[jj].x + pf.y * vf[jj].y
                              + pf.z * vf[jj].z + pf.w * vf[jj].w;
            }
        }
    }

    // write Y [t][h*64+d]
    #pragma unroll
    for (int i = 0; i < 8; i++) {
        float inv = 1.0f / l[i];
        float4 v = make_float4(o[i][0] * inv, o[i][1] * inv, o[i][2] * inv, o[i][3] * inv);
        *(float4*)(g_y + (size_t)(q0 + ty * 8 + i) * DMODEL + h * HDIM + tx * 4) = v;
    }
}

// ---------------- launch ----------------
extern "C" void kernel_launch(void* const* d_in, const int* in_sizes, int n_in,
                              void* d_out, int out_size) {
    const float* x      = (const float*)d_in[0];   // [1,4096,1024]
    const float* w_qkv  = (const float*)d_in[1];   // [1024,3072]
    const float* w_proj = (const float*)d_in[2];   // [1024,1024]
    float* out = (float*)d_out;                    // [1,4096,1024]

    (void)in_sizes; (void)n_in; (void)out_size;

    // attention kernel needs >48KB dynamic smem
    const int attn_smem = 3 * 64 * ATT_PAD * sizeof(float);  // 52224 B
    cudaFuncSetAttribute(attn_kernel, cudaFuncAttributeMaxDynamicSharedMemorySize, attn_smem);

    // 1. RoPE tables
    rope_table_kernel<<<(SEQ * HALF + 255) / 256, 256>>>();

    // 2. QKV projection with scatter into head-major Q/K/V
    {
        dim3 grid(3 * DMODEL / 128, SEQ / 128);   // (24, 32)
        sgemm_kernel<<<grid, 256>>>(x, w_qkv, nullptr, SEQ, 3 * DMODEL, DMODEL, 1);
    }

    // 3. RoPE on Q,K
    rope_apply_kernel<<<(NHEAD * SEQ * HALF + 255) / 256, 256>>>();

    // 4. flash attention
    {
        dim3 grid(SEQ / 64, NHEAD);               // (64, 16)
        attn_kernel<<<grid, 128, attn_smem>>>();
    }

    // 5. output projection
    {
        dim3 grid(DMODEL / 128, SEQ / 128);       // (8, 32)
        sgemm_kernel<<<grid, 256>>>(nullptr, w_proj, out, SEQ, DMODEL, DMODEL, 2);
    }
}

// round 5
// speedup vs baseline: 1.2204x; 1.2204x over previous
#include <cuda_runtime.h>
#include <cuda_bf16.h>
#include <math.h>
#include <stdint.h>

// Problem constants
#define SEQ    4096
#define DMODEL 1024
#define NHEAD  16
#define HDIM   64
#define HALF   32   // HDIM/2

// ---------------- scratch (device globals; no allocation allowed) ----------------
__device__ float g_q[(size_t)NHEAD * SEQ * HDIM];   // [h][t][d]
__device__ float g_k[(size_t)NHEAD * SEQ * HDIM];
__device__ float g_v[(size_t)NHEAD * SEQ * HDIM];
__device__ float g_y[(size_t)SEQ * DMODEL];         // [t][h*64+d]
__device__ float g_cos[SEQ * HALF];
__device__ float g_sin[SEQ * HALF];

// bf16 split operands
__device__ __nv_bfloat16 g_xh[(size_t)SEQ * DMODEL];
__device__ __nv_bfloat16 g_xl[(size_t)SEQ * DMODEL];
__device__ __nv_bfloat16 g_yh[(size_t)SEQ * DMODEL];
__device__ __nv_bfloat16 g_yl[(size_t)SEQ * DMODEL];
__device__ __nv_bfloat16 g_wqh[(size_t)3 * DMODEL * DMODEL];  // w_qkv^T [3072][1024]
__device__ __nv_bfloat16 g_wql[(size_t)3 * DMODEL * DMODEL];
__device__ __nv_bfloat16 g_wph[(size_t)DMODEL * DMODEL];      // w_proj^T [1024][1024]
__device__ __nv_bfloat16 g_wpl[(size_t)DMODEL * DMODEL];

// ---------------- helpers ----------------
__device__ __forceinline__ uint32_t smem_to_u32(const void* p) {
    uint32_t a;
    asm("{ .reg .u64 t; cvta.to.shared.u64 t, %1; cvt.u32.u64 %0, t; }" : "=r"(a) : "l"(p));
    return a;
}
__device__ __forceinline__ void ldsm4(uint32_t addr, uint32_t r[4]) {
    asm volatile("ldmatrix.sync.aligned.m8n8.x4.shared.b16 {%0,%1,%2,%3}, [%4];"
                 : "=r"(r[0]), "=r"(r[1]), "=r"(r[2]), "=r"(r[3]) : "r"(addr));
}
__device__ __forceinline__ void mma16816(float c[4], const uint32_t a[4], uint32_t b0, uint32_t b1) {
    asm volatile("mma.sync.aligned.m16n8k16.row.col.f32.bf16.bf16.f32 "
                 "{%0,%1,%2,%3}, {%4,%5,%6,%7}, {%8,%9}, {%0,%1,%2,%3};"
                 : "+f"(c[0]), "+f"(c[1]), "+f"(c[2]), "+f"(c[3])
                 : "r"(a[0]), "r"(a[1]), "r"(a[2]), "r"(a[3]), "r"(b0), "r"(b1));
}

// ---------------- RoPE cos/sin table ----------------
__global__ void rope_table_kernel() {
    int idx = blockIdx.x * blockDim.x + threadIdx.x;
    if (idx >= SEQ * HALF) return;
    int d = idx & (HALF - 1);
    int t = idx >> 5;
    double inv = exp(-log(10000.0) * (double)d / (double)HALF);
    float invf = (float)inv;
    float f = (float)t * invf;
    g_cos[idx] = (float)cos((double)f);
    g_sin[idx] = (float)sin((double)f);
}

// ---------------- RoPE apply (in-place on g_q, g_k) ----------------
__global__ void rope_apply_kernel() {
    int idx = blockIdx.x * blockDim.x + threadIdx.x;
    if (idx >= NHEAD * SEQ * HALF) return;
    int d = idx & (HALF - 1);
    int t = (idx >> 5) & (SEQ - 1);
    int h = idx >> 17;
    float c = g_cos[t * HALF + d];
    float s = g_sin[t * HALF + d];
    size_t base = ((size_t)h * SEQ + t) * HDIM;
    float q1 = g_q[base + d];
    float q2 = g_q[base + d + HALF];
    g_q[base + d]        = q1 * c - q2 * s;
    g_q[base + d + HALF] = q2 * c + q1 * s;
    float k1 = g_k[base + d];
    float k2 = g_k[base + d + HALF];
    g_k[base + d]        = k1 * c - k2 * s;
    g_k[base + d + HALF] = k2 * c + k1 * s;
}

// ---------------- fp32 -> bf16 hi/lo split ----------------
__global__ void split_kernel(const float* __restrict__ src, __nv_bfloat16* __restrict__ hi,
                             __nv_bfloat16* __restrict__ lo, int n) {
    int i = blockIdx.x * blockDim.x + threadIdx.x;
    if (i >= n) return;
    float v = src[i];
    __nv_bfloat16 h = __float2bfloat16(v);
    hi[i] = h;
    lo[i] = __float2bfloat16(v - __bfloat162float(h));
}

// ---------------- transpose + split: W[K][N] -> Wt hi/lo [N][K] ----------------
__global__ void transpose_split_kernel(const float* __restrict__ W,
                                       __nv_bfloat16* __restrict__ Th,
                                       __nv_bfloat16* __restrict__ Tl, int K, int N) {
    __shared__ float t[32][33];
    int n0 = blockIdx.x * 32, k0 = blockIdx.y * 32;
    int tx = threadIdx.x, ty = threadIdx.y;
    #pragma unroll
    for (int r = 0; r < 4; r++)
        t[ty + 8 * r][tx] = W[(size_t)(k0 + ty + 8 * r) * N + n0 + tx];
    __syncthreads();
    #pragma unroll
    for (int r = 0; r < 4; r++) {
        float v = t[tx][ty + 8 * r];
        __nv_bfloat16 h = __float2bfloat16(v);
        size_t o = (size_t)(n0 + ty + 8 * r) * K + k0 + tx;
        Th[o] = h;
        Tl[o] = __float2bfloat16(v - __bfloat162float(h));
    }
}

// ---------------- mma.sync bf16 split-3 GEMM ----------------
// C[M,N] = A @ B; A bf16 hi/lo [M][K]; B transposed bf16 hi/lo [N][K].
// CTA 128x128, BK=32, 8 warps (4x2), warp tile 32x64, double-buffered smem.
#define BKC 32
#define TS 40                          // bf16 per smem row (80B, 16B-aligned, ldmatrix conflict-free)
#define TILE_ELEMS (128 * TS)          // 5120 bf16
#define TILE_BYTES (TILE_ELEMS * 2)    // 10240
#define GEMM_SMEM (8 * TILE_BYTES)     // 2 buffers x 4 tiles = 81920 B

__global__ __launch_bounds__(256, 1) void gemm_mma_kernel(
    const __nv_bfloat16* __restrict__ Ah, const __nv_bfloat16* __restrict__ Al,
    const __nv_bfloat16* __restrict__ Bh, const __nv_bfloat16* __restrict__ Bl,
    float* __restrict__ C, float* __restrict__ Q, float* __restrict__ Kp,
    float* __restrict__ V, int N, int K, int mode)
{
    extern __shared__ __nv_bfloat16 sm_g[];
    const int tid = threadIdx.x;
    const int wid = tid >> 5, lid = tid & 31;
    const int brow = blockIdx.y * 128, bcol = blockIdx.x * 128;
    const int wm = wid >> 1, wn = wid & 1;
    const uint32_t smem_base = smem_to_u32(sm_g);

    const __nv_bfloat16* srcs[4] = { Ah, Al, Bh, Bl };

    float acc[2][8][4];
    #pragma unroll
    for (int mi = 0; mi < 2; mi++)
        #pragma unroll
        for (int ni = 0; ni < 8; ni++)
            #pragma unroll
            for (int r = 0; r < 4; r++) acc[mi][ni][r] = 0.f;

    // ldmatrix lane offsets
    const int rowA = lid & 15;
    const int koA  = (lid >> 4) << 3;
    const int rowB = (lid & 7) + ((lid >> 4) << 3);
    const int koB  = ((lid >> 3) & 1) << 3;

    float4 pre[8];

    auto load_regs = [&](int c) {
        #pragma unroll
        for (int t = 0; t < 4; t++) {
            const __nv_bfloat16* s = srcs[t];
            const int rb = (t < 2) ? brow : bcol;
            #pragma unroll
            for (int j = 0; j < 2; j++) {
                int idx = tid + j * 256;
                int row = idx >> 2, g = idx & 3;
                pre[t * 2 + j] = *(const float4*)(s + (size_t)(rb + row) * K + c * BKC + g * 8);
            }
        }
    };
    auto store_smem = [&](int b) {
        #pragma unroll
        for (int t = 0; t < 4; t++) {
            __nv_bfloat16* d = sm_g + (b * 4 + t) * TILE_ELEMS;
            #pragma unroll
            for (int j = 0; j < 2; j++) {
                int idx = tid + j * 256;
                int row = idx >> 2, g = idx & 3;
                *(float4*)(d + row * TS + g * 8) = pre[t * 2 + j];
            }
        }
    };
    auto compute = [&](int b) {
        const uint32_t bA_h = smem_base + (uint32_t)(b * 4 + 0) * TILE_BYTES;
        const uint32_t bA_l = smem_base + (uint32_t)(b * 4 + 1) * TILE_BYTES;
        const uint32_t bB_h = smem_base + (uint32_t)(b * 4 + 2) * TILE_BYTES;
        const uint32_t bB_l = smem_base + (uint32_t)(b * 4 + 3) * TILE_BYTES;
        #pragma unroll
        for (int ks = 0; ks < 2; ks++) {
            uint32_t ah[2][4], al[2][4];
            #pragma unroll
            for (int mi = 0; mi < 2; mi++) {
                uint32_t off = ((uint32_t)(wm * 32 + mi * 16 + rowA) * TS + ks * 16 + koA) * 2;
                ldsm4(bA_h + off, ah[mi]);
                ldsm4(bA_l + off, al[mi]);
            }
            #pragma unroll
            for (int ni2 = 0; ni2 < 4; ni2++) {
                uint32_t off = ((uint32_t)(wn * 64 + ni2 * 16 + rowB) * TS + ks * 16 + koB) * 2;
                uint32_t bh[4], bl[4];
                ldsm4(bB_h + off, bh);
                ldsm4(bB_l + off, bl);
                #pragma unroll
                for (int half = 0; half < 2; half++) {
                    const int ni = ni2 * 2 + half;
                    const uint32_t bh0 = bh[half * 2], bh1 = bh[half * 2 + 1];
                    const uint32_t bl0 = bl[half * 2], bl1 = bl[half * 2 + 1];
                    #pragma unroll
                    for (int mi = 0; mi < 2; mi++) {
                        mma16816(acc[mi][ni], ah[mi], bh0, bh1);
                        mma16816(acc[mi][ni], ah[mi], bl0, bl1);
                        mma16816(acc[mi][ni], al[mi], bh0, bh1);
                    }
                }
            }
        }
    };

    const int nc = K / BKC;
    load_regs(0);
    store_smem(0);
    for (int c = 0; c < nc; c++) {
        __syncthreads();
        if (c + 1 < nc) load_regs(c + 1);
        compute(c & 1);
        if (c + 1 < nc) store_smem((c + 1) & 1);
    }

    // epilogue: direct float2 stores
    #pragma unroll
    for (int mi = 0; mi < 2; mi++) {
        #pragma unroll
        for (int ni = 0; ni < 8; ni++) {
            int row0 = brow + wm * 32 + mi * 16 + (lid >> 2);
            int col  = bcol + wn * 64 + ni * 8 + (lid & 3) * 2;
            if (mode == 1) {
                int sect = col >> 10, nn = col & 1023, h = nn >> 6, d = nn & 63;
                float* dst = (sect == 0) ? Q : (sect == 1) ? Kp : V;
                *(float2*)&dst[((size_t)h * SEQ + row0) * HDIM + d] =
                    make_float2(acc[mi][ni][0], acc[mi][ni][1]);
                *(float2*)&dst[((size_t)h * SEQ + row0 + 8) * HDIM + d] =
                    make_float2(acc[mi][ni][2], acc[mi][ni][3]);
            } else {
                *(float2*)&C[(size_t)row0 * N + col] =
                    make_float2(acc[mi][ni][0], acc[mi][ni][1]);
                *(float2*)&C[(size_t)(row0 + 8) * N + col] =
                    make_float2(acc[mi][ni][2], acc[mi][ni][3]);
            }
        }
    }
}

// ---------------- Flash attention (fp32, causal) — unchanged ----------------
#define ATT_PAD 68
__global__ __launch_bounds__(128) void attn_kernel() {
    extern __shared__ float sm[];
    float (*Qs)[ATT_PAD] = (float(*)[ATT_PAD])(sm);
    float (*Ks)[ATT_PAD] = (float(*)[ATT_PAD])(sm + 64 * ATT_PAD);
    float (*Vt)[ATT_PAD] = (float(*)[ATT_PAD])(sm + 2 * 64 * ATT_PAD);

    const int tid = threadIdx.x;
    const int tx  = tid & 15;
    const int ty  = tid >> 4;
    const int h   = blockIdx.y;
    const int qt  = blockIdx.x;
    const int q0  = qt * 64;

    const float* __restrict__ Qh = g_q + (size_t)h * SEQ * HDIM;
    const float* __restrict__ Kh = g_k + (size_t)h * SEQ * HDIM;
    const float* __restrict__ Vh = g_v + (size_t)h * SEQ * HDIM;

    for (int i = tid; i < 64 * 16; i += 128) {
        int row = i >> 4, c4 = (i & 15) << 2;
        *(float4*)&Qs[row][c4] = *(const float4*)(Qh + (size_t)(q0 + row) * HDIM + c4);
    }

    float m[8], l[8], o[8][4];
    #pragma unroll
    for (int i = 0; i < 8; i++) {
        m[i] = -1e30f; l[i] = 0.f;
        #pragma unroll
        for (int j = 0; j < 4; j++) o[i][j] = 0.f;
    }

    for (int j = 0; j <= qt; j++) {
        __syncthreads();
        for (int i = tid; i < 64 * 16; i += 128) {
            int row = i >> 4, c4 = (i & 15) << 2;
            size_t g = (size_t)(j * 64 + row) * HDIM + c4;
            *(float4*)&Ks[row][c4] = *(const float4*)(Kh + g);
            float4 vv = *(const float4*)(Vh + g);
            Vt[c4 + 0][row] = vv.x;
            Vt[c4 + 1][row] = vv.y;
            Vt[c4 + 2][row] = vv.z;
            Vt[c4 + 3][row] = vv.w;
        }
        __syncthreads();

        float s[8][4];
        #pragma unroll
        for (int i = 0; i < 8; i++)
            #pragma unroll
            for (int jj = 0; jj < 4; jj++) s[i][jj] = 0.f;

        #pragma unroll
        for (int kk = 0; kk < 64; kk += 4) {
            float4 kf[4];
            #pragma unroll
            for (int jj = 0; jj < 4; jj++)
                kf[jj] = *(const float4*)&Ks[tx * 4 + jj][kk];
            #pragma unroll
            for (int i = 0; i < 8; i++) {
                float4 qf = *(const float4*)&Qs[ty * 8 + i][kk];
                #pragma unroll
                for (int jj = 0; jj < 4; jj++)
                    s[i][jj] += qf.x * kf[jj].x + qf.y * kf[jj].y
                              + qf.z * kf[jj].z + qf.w * kf[jj].w;
            }
        }

        const bool diag = (j == qt);
        #pragma unroll
        for (int i = 0; i < 8; i++) {
            int qrow = q0 + ty * 8 + i;
            float mx = -1e30f;
            #pragma unroll
            for (int jj = 0; jj < 4; jj++) {
                float v = s[i][jj] * 0.125f;
                if (diag && (j * 64 + tx * 4 + jj) > qrow) v = -1e30f;
                s[i][jj] = v;
                mx = fmaxf(mx, v);
            }
            mx = fmaxf(mx, __shfl_xor_sync(0xffffffffu, mx, 8, 16));
            mx = fmaxf(mx, __shfl_xor_sync(0xffffffffu, mx, 4, 16));
            mx = fmaxf(mx, __shfl_xor_sync(0xffffffffu, mx, 2, 16));
            mx = fmaxf(mx, __shfl_xor_sync(0xffffffffu, mx, 1, 16));
            float mnew = fmaxf(m[i], mx);
            float corr = expf(m[i] - mnew);
            float rs = 0.f;
            #pragma unroll
            for (int jj = 0; jj < 4; jj++) {
                float p = expf(s[i][jj] - mnew);
                s[i][jj] = p;
                rs += p;
            }
            rs += __shfl_xor_sync(0xffffffffu, rs, 8, 16);
            rs += __shfl_xor_sync(0xffffffffu, rs, 4, 16);
            rs += __shfl_xor_sync(0xffffffffu, rs, 2, 16);
            rs += __shfl_xor_sync(0xffffffffu, rs, 1, 16);
            l[i] = l[i] * corr + rs;
            m[i] = mnew;
            #pragma unroll
            for (int jj = 0; jj < 4; jj++) o[i][jj] *= corr;
        }

        __syncthreads();
        #pragma unroll
        for (int i = 0; i < 8; i++)
            #pragma unroll
            for (int jj = 0; jj < 4; jj++)
                Ks[ty * 8 + i][tx * 4 + jj] = s[i][jj];
        __syncthreads();

        #pragma unroll
        for (int kk = 0; kk < 64; kk += 4) {
            float4 vf[4];
            #pragma unroll
            for (int jj = 0; jj < 4; jj++)
                vf[jj] = *(const float4*)&Vt[tx * 4 + jj][kk];
            #pragma unroll
            for (int i = 0; i < 8; i++) {
                float4 pf = *(const float4*)&Ks[ty * 8 + i][kk];
                #pragma unroll
                for (int jj = 0; jj < 4; jj++)
                    o[i][jj] += pf.x * vf[jj].x + pf.y * vf[jj].y
                              + pf.z * vf[jj].z + pf.w * vf[jj].w;
            }
        }
    }

    #pragma unroll
    for (int i = 0; i < 8; i++) {
        float inv = 1.0f / l[i];
        float4 v = make_float4(o[i][0] * inv, o[i][1] * inv, o[i][2] * inv, o[i][3] * inv);
        *(float4*)(g_y + (size_t)(q0 + ty * 8 + i) * DMODEL + h * HDIM + tx * 4) = v;
    }
}

// ---------------- launch ----------------
extern "C" void kernel_launch(void* const* d_in, const int* in_sizes, int n_in,
                              void* d_out, int out_size) {
    const float* x      = (const float*)d_in[0];   // [1,4096,1024]
    const float* w_qkv  = (const float*)d_in[1];   // [1024,3072]
    const float* w_proj = (const float*)d_in[2];   // [1024,1024]
    float* out = (float*)d_out;                    // [1,4096,1024]
    (void)in_sizes; (void)n_in; (void)out_size;

    // Resolve DEVICE addresses of scratch globals (host-side symbol shadows are
    // NOT device pointers — round-4 bug).
    float *p_q, *p_k, *p_v, *p_y;
    __nv_bfloat16 *p_xh, *p_xl, *p_yh, *p_yl, *p_wqh, *p_wql, *p_wph, *p_wpl;
    cudaGetSymbolAddress((void**)&p_q,  g_q);
    cudaGetSymbolAddress((void**)&p_k,  g_k);
    cudaGetSymbolAddress((void**)&p_v,  g_v);
    cudaGetSymbolAddress((void**)&p_y,  g_y);
    cudaGetSymbolAddress((void**)&p_xh, g_xh);
    cudaGetSymbolAddress((void**)&p_xl, g_xl);
    cudaGetSymbolAddress((void**)&p_yh, g_yh);
    cudaGetSymbolAddress((void**)&p_yl, g_yl);
    cudaGetSymbolAddress((void**)&p_wqh, g_wqh);
    cudaGetSymbolAddress((void**)&p_wql, g_wql);
    cudaGetSymbolAddress((void**)&p_wph, g_wph);
    cudaGetSymbolAddress((void**)&p_wpl, g_wpl);

    const int attn_smem = 3 * 64 * ATT_PAD * sizeof(float);   // 52224 B
    cudaFuncSetAttribute(attn_kernel, cudaFuncAttributeMaxDynamicSharedMemorySize, attn_smem);
    cudaFuncSetAttribute(gemm_mma_kernel, cudaFuncAttributeMaxDynamicSharedMemorySize, GEMM_SMEM);

    // 1. RoPE tables
    rope_table_kernel<<<(SEQ * HALF + 255) / 256, 256>>>();

    // 2. operand prep: x split, w_qkv transpose+split
    split_kernel<<<(SEQ * DMODEL + 255) / 256, 256>>>(x, p_xh, p_xl, SEQ * DMODEL);
    {
        dim3 grid(3 * DMODEL / 32, DMODEL / 32);
        transpose_split_kernel<<<grid, dim3(32, 8)>>>(w_qkv, p_wqh, p_wql, DMODEL, 3 * DMODEL);
    }

    // 3. QKV projection (mma.sync bf16 split-3) with scatter into head-major Q/K/V
    {
        dim3 grid(3 * DMODEL / 128, SEQ / 128);   // (24, 32)
        gemm_mma_kernel<<<grid, 256, GEMM_SMEM>>>(p_xh, p_xl, p_wqh, p_wql,
                                                  nullptr, p_q, p_k, p_v,
                                                  3 * DMODEL, DMODEL, 1);
    }

    // 4. RoPE on Q,K
    rope_apply_kernel<<<(NHEAD * SEQ * HALF + 255) / 256, 256>>>();

    // 5. flash attention
    {
        dim3 grid(SEQ / 64, NHEAD);               // (64, 16)
        attn_kernel<<<grid, 128, attn_smem>>>();
    }

    // 6. output projection prep + GEMM
    split_kernel<<<(SEQ * DMODEL + 255) / 256, 256>>>(p_y, p_yh, p_yl, SEQ * DMODEL);
    {
        dim3 grid(DMODEL / 32, DMODEL / 32);
        transpose_split_kernel<<<grid, dim3(32, 8)>>>(w_proj, p_wph, p_wpl, DMODEL, DMODEL);
    }
    {
        dim3 grid(DMODEL / 128, SEQ / 128);       // (8, 32)
        gemm_mma_kernel<<<grid, 256, GEMM_SMEM>>>(p_yh, p_yl, p_wph, p_wpl,
                                                  out, nullptr, nullptr, nullptr,
                                                  DMODEL, DMODEL, 0);
    }
}

// round 6
// speedup vs baseline: 4.1064x; 3.3649x over previous
#include <cuda_runtime.h>
#include <cuda_bf16.h>
#include <math.h>
#include <stdint.h>

// Problem constants
#define SEQ    4096
#define DMODEL 1024
#define NHEAD  16
#define HDIM   64
#define HALF   32   // HDIM/2

// ---------------- scratch (device globals) ----------------
__device__ float g_q[(size_t)NHEAD * SEQ * HDIM];   // [h][t][d] fp32 (pre-RoPE)
__device__ float g_k[(size_t)NHEAD * SEQ * HDIM];
__device__ float g_v[(size_t)NHEAD * SEQ * HDIM];
__device__ float g_y[(size_t)SEQ * DMODEL];         // [t][h*64+d]
__device__ float g_cos[SEQ * HALF];
__device__ float g_sin[SEQ * HALF];

// bf16 split operands for projections
__device__ __nv_bfloat16 g_xh[(size_t)SEQ * DMODEL];
__device__ __nv_bfloat16 g_xl[(size_t)SEQ * DMODEL];
__device__ __nv_bfloat16 g_yh[(size_t)SEQ * DMODEL];
__device__ __nv_bfloat16 g_yl[(size_t)SEQ * DMODEL];
__device__ __nv_bfloat16 g_wqh[(size_t)3 * DMODEL * DMODEL];
__device__ __nv_bfloat16 g_wql[(size_t)3 * DMODEL * DMODEL];
__device__ __nv_bfloat16 g_wph[(size_t)DMODEL * DMODEL];
__device__ __nv_bfloat16 g_wpl[(size_t)DMODEL * DMODEL];

// bf16 split operands for attention (RoPE'd; q pre-scaled by 1/8)
__device__ __nv_bfloat16 g_qbh[(size_t)NHEAD * SEQ * HDIM];  // [h][t][d]
__device__ __nv_bfloat16 g_qbl[(size_t)NHEAD * SEQ * HDIM];
__device__ __nv_bfloat16 g_kbh[(size_t)NHEAD * SEQ * HDIM];
__device__ __nv_bfloat16 g_kbl[(size_t)NHEAD * SEQ * HDIM];
__device__ __nv_bfloat16 g_vth[(size_t)NHEAD * HDIM * SEQ]; // [h][d][t]  (V^T)
__device__ __nv_bfloat16 g_vtl[(size_t)NHEAD * HDIM * SEQ];

// ---------------- helpers ----------------
__device__ __forceinline__ uint32_t smem_to_u32(const void* p) {
    uint32_t a;
    asm("{ .reg .u64 t; cvta.to.shared.u64 t, %1; cvt.u32.u64 %0, t; }" : "=r"(a) : "l"(p));
    return a;
}
__device__ __forceinline__ void ldsm4(uint32_t addr, uint32_t r[4]) {
    asm volatile("ldmatrix.sync.aligned.m8n8.x4.shared.b16 {%0,%1,%2,%3}, [%4];"
                 : "=r"(r[0]), "=r"(r[1]), "=r"(r[2]), "=r"(r[3]) : "r"(addr));
}
__device__ __forceinline__ void mma16816(float c[4], const uint32_t a[4], uint32_t b0, uint32_t b1) {
    asm volatile("mma.sync.aligned.m16n8k16.row.col.f32.bf16.bf16.f32 "
                 "{%0,%1,%2,%3}, {%4,%5,%6,%7}, {%8,%9}, {%0,%1,%2,%3};"
                 : "+f"(c[0]), "+f"(c[1]), "+f"(c[2]), "+f"(c[3])
                 : "r"(a[0]), "r"(a[1]), "r"(a[2]), "r"(a[3]), "r"(b0), "r"(b1));
}
#define CP16(dst, src) \
    asm volatile("cp.async.ca.shared.global [%0], [%1], 16;" :: "r"(dst), "l"(__cvta_generic_to_global(src)))
#define CP_COMMIT() asm volatile("cp.async.commit_group;")
#define CP_WAIT(N)  asm volatile("cp.async.wait_group %0;" :: "n"(N))

__device__ __forceinline__ uint32_t pack_bf16(float a, float b) {
    __nv_bfloat162 h = __floats2bfloat162_rn(a, b);
    return *(uint32_t*)&h;
}

// ---------------- RoPE cos/sin table ----------------
__global__ void rope_table_kernel() {
    int idx = blockIdx.x * blockDim.x + threadIdx.x;
    if (idx >= SEQ * HALF) return;
    int d = idx & (HALF - 1);
    int t = idx >> 5;
    double inv = exp(-log(10000.0) * (double)d / (double)HALF);
    float invf = (float)inv;
    float f = (float)t * invf;
    g_cos[idx] = (float)cos((double)f);
    g_sin[idx] = (float)sin((double)f);
}

// ---------------- RoPE + bf16-split + V transpose ----------------
// block: (t-tile 64, head). Writes q (scaled 1/8), k as [h][t][d] hi/lo; v as [h][d][t] hi/lo.
__global__ __launch_bounds__(256) void rope_split_kernel() {
    __shared__ float vs[64][65];
    const int h = blockIdx.y, t0 = blockIdx.x * 64;
    const int tid = threadIdx.x;
    const size_t base_ht = ((size_t)h * SEQ + t0) * HDIM;

    #pragma unroll
    for (int i = 0; i < 8; i++) {
        int p = tid + i * 256;             // 2048 pairs
        int tl = p >> 5, d = p & 31;
        int t = t0 + tl;
        float c = g_cos[t * HALF + d], s = g_sin[t * HALF + d];
        size_t b = base_ht + (size_t)tl * HDIM;
        float q1 = g_q[b + d], q2 = g_q[b + d + HALF];
        float r1 = (q1 * c - q2 * s) * 0.125f;
        float r2 = (q2 * c + q1 * s) * 0.125f;
        __nv_bfloat16 h1 = __float2bfloat16(r1);
        __nv_bfloat16 h2 = __float2bfloat16(r2);
        g_qbh[b + d] = h1;        g_qbl[b + d] = __float2bfloat16(r1 - __bfloat162float(h1));
        g_qbh[b + d + HALF] = h2; g_qbl[b + d + HALF] = __float2bfloat16(r2 - __bfloat162float(h2));
        float k1 = g_k[b + d], k2 = g_k[b + d + HALF];
        float s1 = k1 * c - k2 * s;
        float s2 = k2 * c + k1 * s;
        __nv_bfloat16 kh1 = __float2bfloat16(s1);
        __nv_bfloat16 kh2 = __float2bfloat16(s2);
        g_kbh[b + d] = kh1;        g_kbl[b + d] = __float2bfloat16(s1 - __bfloat162float(kh1));
        g_kbh[b + d + HALF] = kh2; g_kbl[b + d + HALF] = __float2bfloat16(s2 - __bfloat162float(kh2));
    }

    // V transpose + split
    #pragma unroll
    for (int i = 0; i < 16; i++) {
        int idx = tid + i * 256;           // 4096
        int tl = idx >> 6, d = idx & 63;
        vs[tl][d] = g_v[base_ht + (size_t)tl * HDIM + d];
    }
    __syncthreads();
    #pragma unroll
    for (int i = 0; i < 16; i++) {
        int idx = tid + i * 256;
        int d = idx >> 6, tl = idx & 63;
        float v = vs[tl][d];
        __nv_bfloat16 hv = __float2bfloat16(v);
        size_t o = ((size_t)h * HDIM + d) * SEQ + t0 + tl;
        g_vth[o] = hv;
        g_vtl[o] = __float2bfloat16(v - __bfloat162float(hv));
    }
}

// ---------------- fp32 -> bf16 hi/lo split ----------------
__global__ void split_kernel(const float* __restrict__ src, __nv_bfloat16* __restrict__ hi,
                             __nv_bfloat16* __restrict__ lo, int n) {
    int i = blockIdx.x * blockDim.x + threadIdx.x;
    if (i >= n) return;
    float v = src[i];
    __nv_bfloat16 h = __float2bfloat16(v);
    hi[i] = h;
    lo[i] = __float2bfloat16(v - __bfloat162float(h));
}

// ---------------- transpose + split: W[K][N] -> Wt hi/lo [N][K] ----------------
__global__ void transpose_split_kernel(const float* __restrict__ W,
                                       __nv_bfloat16* __restrict__ Th,
                                       __nv_bfloat16* __restrict__ Tl, int K, int N) {
    __shared__ float t[32][33];
    int n0 = blockIdx.x * 32, k0 = blockIdx.y * 32;
    int tx = threadIdx.x, ty = threadIdx.y;
    #pragma unroll
    for (int r = 0; r < 4; r++)
        t[ty + 8 * r][tx] = W[(size_t)(k0 + ty + 8 * r) * N + n0 + tx];
    __syncthreads();
    #pragma unroll
    for (int r = 0; r < 4; r++) {
        float v = t[tx][ty + 8 * r];
        __nv_bfloat16 h = __float2bfloat16(v);
        size_t o = (size_t)(n0 + ty + 8 * r) * K + k0 + tx;
        Th[o] = h;
        Tl[o] = __float2bfloat16(v - __bfloat162float(h));
    }
}

// ---------------- mma.sync bf16 split-3 GEMM (validated round 5) ----------------
#define BKC 32
#define TS 40
#define TILE_ELEMS (128 * TS)
#define TILE_BYTES (TILE_ELEMS * 2)
#define GEMM_SMEM (8 * TILE_BYTES)

__global__ __launch_bounds__(256, 1) void gemm_mma_kernel(
    const __nv_bfloat16* __restrict__ Ah, const __nv_bfloat16* __restrict__ Al,
    const __nv_bfloat16* __restrict__ Bh, const __nv_bfloat16* __restrict__ Bl,
    float* __restrict__ C, float* __restrict__ Q, float* __restrict__ Kp,
    float* __restrict__ V, int N, int K, int mode)
{
    extern __shared__ __nv_bfloat16 sm_g[];
    const int tid = threadIdx.x;
    const int wid = tid >> 5, lid = tid & 31;
    const int brow = blockIdx.y * 128, bcol = blockIdx.x * 128;
    const int wm = wid >> 1, wn = wid & 1;
    const uint32_t smem_base = smem_to_u32(sm_g);

    const __nv_bfloat16* srcs[4] = { Ah, Al, Bh, Bl };

    float acc[2][8][4];
    #pragma unroll
    for (int mi = 0; mi < 2; mi++)
        #pragma unroll
        for (int ni = 0; ni < 8; ni++)
            #pragma unroll
            for (int r = 0; r < 4; r++) acc[mi][ni][r] = 0.f;

    const int rowA = lid & 15;
    const int koA  = (lid >> 4) << 3;
    const int rowB = (lid & 7) + ((lid >> 4) << 3);
    const int koB  = ((lid >> 3) & 1) << 3;

    float4 pre[8];

    auto load_regs = [&](int c) {
        #pragma unroll
        for (int t = 0; t < 4; t++) {
            const __nv_bfloat16* s = srcs[t];
            const int rb = (t < 2) ? brow : bcol;
            #pragma unroll
            for (int j = 0; j < 2; j++) {
                int idx = tid + j * 256;
                int row = idx >> 2, g = idx & 3;
                pre[t * 2 + j] = *(const float4*)(s + (size_t)(rb + row) * K + c * BKC + g * 8);
            }
        }
    };
    auto store_smem = [&](int b) {
        #pragma unroll
        for (int t = 0; t < 4; t++) {
            __nv_bfloat16* d = sm_g + (b * 4 + t) * TILE_ELEMS;
            #pragma unroll
            for (int j = 0; j < 2; j++) {
                int idx = tid + j * 256;
                int row = idx >> 2, g = idx & 3;
                *(float4*)(d + row * TS + g * 8) = pre[t * 2 + j];
            }
        }
    };
    auto compute = [&](int b) {
        const uint32_t bA_h = smem_base + (uint32_t)(b * 4 + 0) * TILE_BYTES;
        const uint32_t bA_l = smem_base + (uint32_t)(b * 4 + 1) * TILE_BYTES;
        const uint32_t bB_h = smem_base + (uint32_t)(b * 4 + 2) * TILE_BYTES;
        const uint32_t bB_l = smem_base + (uint32_t)(b * 4 + 3) * TILE_BYTES;
        #pragma unroll
        for (int ks = 0; ks < 2; ks++) {
            uint32_t ah[2][4], al[2][4];
            #pragma unroll
            for (int mi = 0; mi < 2; mi++) {
                uint32_t off = ((uint32_t)(wm * 32 + mi * 16 + rowA) * TS + ks * 16 + koA) * 2;
                ldsm4(bA_h + off, ah[mi]);
                ldsm4(bA_l + off, al[mi]);
            }
            #pragma unroll
            for (int ni2 = 0; ni2 < 4; ni2++) {
                uint32_t off = ((uint32_t)(wn * 64 + ni2 * 16 + rowB) * TS + ks * 16 + koB) * 2;
                uint32_t bh[4], bl[4];
                ldsm4(bB_h + off, bh);
                ldsm4(bB_l + off, bl);
                #pragma unroll
                for (int half = 0; half < 2; half++) {
                    const int ni = ni2 * 2 + half;
                    const uint32_t bh0 = bh[half * 2], bh1 = bh[half * 2 + 1];
                    const uint32_t bl0 = bl[half * 2], bl1 = bl[half * 2 + 1];
                    #pragma unroll
                    for (int mi = 0; mi < 2; mi++) {
                        mma16816(acc[mi][ni], ah[mi], bh0, bh1);
                        mma16816(acc[mi][ni], ah[mi], bl0, bl1);
                        mma16816(acc[mi][ni], al[mi], bh0, bh1);
                    }
                }
            }
        }
    };

    const int nc = K / BKC;
    load_regs(0);
    store_smem(0);
    for (int c = 0; c < nc; c++) {
        __syncthreads();
        if (c + 1 < nc) load_regs(c + 1);
        compute(c & 1);
        if (c + 1 < nc) store_smem((c + 1) & 1);
    }

    #pragma unroll
    for (int mi = 0; mi < 2; mi++) {
        #pragma unroll
        for (int ni = 0; ni < 8; ni++) {
            int row0 = brow + wm * 32 + mi * 16 + (lid >> 2);
            int col  = bcol + wn * 64 + ni * 8 + (lid & 3) * 2;
            if (mode == 1) {
                int sect = col >> 10, nn = col & 1023, h = nn >> 6, d = nn & 63;
                float* dst = (sect == 0) ? Q : (sect == 1) ? Kp : V;
                *(float2*)&dst[((size_t)h * SEQ + row0) * HDIM + d] =
                    make_float2(acc[mi][ni][0], acc[mi][ni][1]);
                *(float2*)&dst[((size_t)h * SEQ + row0 + 8) * HDIM + d] =
                    make_float2(acc[mi][ni][2], acc[mi][ni][3]);
            } else {
                *(float2*)&C[(size_t)row0 * N + col] =
                    make_float2(acc[mi][ni][0], acc[mi][ni][1]);
                *(float2*)&C[(size_t)(row0 + 8) * N + col] =
                    make_float2(acc[mi][ni][2], acc[mi][ni][3]);
            }
        }
    }
}

// ---------------- Flash attention via mma.sync (bf16 split, causal) ----------------
// Block per (q-tile 128, head). 256 threads = 8 warps, each warp m16 x full width.
#define PADK 72                         // K/Q tile row pitch (bf16), conflict-free ldmatrix
#define PADV 136                        // V^T tile row pitch
#define KT_B (128 * PADK * 2)           // 18432 B
#define VT_B (64 * PADV * 2)            // 17408 B
#define BUF_B (2 * KT_B + 2 * VT_B)     // 71680 B
#define ATTN_SMEM (2 * BUF_B)           // 143360 B

__global__ __launch_bounds__(256, 1) void attn_mma_kernel(
    const __nv_bfloat16* __restrict__ Qbh, const __nv_bfloat16* __restrict__ Qbl,
    const __nv_bfloat16* __restrict__ Kbh, const __nv_bfloat16* __restrict__ Kbl,
    const __nv_bfloat16* __restrict__ Vth, const __nv_bfloat16* __restrict__ Vtl,
    float* __restrict__ Y)
{
    extern __shared__ char asmem[];
    const uint32_t sb = smem_to_u32(asmem);
    const int tid = threadIdx.x;
    const int wid = tid >> 5, lid = tid & 31;
    const int h = blockIdx.y, qt = blockIdx.x;
    const int q0 = qt * 128;

    const __nv_bfloat16* pQh = Qbh + (size_t)h * SEQ * HDIM;
    const __nv_bfloat16* pQl = Qbl + (size_t)h * SEQ * HDIM;
    const __nv_bfloat16* pKh = Kbh + (size_t)h * SEQ * HDIM;
    const __nv_bfloat16* pKl = Kbl + (size_t)h * SEQ * HDIM;
    const __nv_bfloat16* pVh = Vth + (size_t)h * HDIM * SEQ;
    const __nv_bfloat16* pVl = Vtl + (size_t)h * HDIM * SEQ;

    // --- stage Q tile into buf1 K-areas, ldmatrix to registers ---
    #pragma unroll
    for (int i = 0; i < 4; i++) {
        int idx = tid + i * 256;              // 1024 float4 slots
        int row = idx >> 3, g = idx & 7;
        *(float4*)(asmem + BUF_B + row * (PADK * 2) + g * 16) =
            *(const float4*)(pQh + (size_t)(q0 + row) * HDIM + g * 8);
        *(float4*)(asmem + BUF_B + KT_B + row * (PADK * 2) + g * 16) =
            *(const float4*)(pQl + (size_t)(q0 + row) * HDIM + g * 8);
    }
    __syncthreads();

    const int rowA = lid & 15;
    const int koA  = (lid >> 4) << 3;
    const int rowB = (lid & 7) + ((lid >> 4) << 3);
    const int koB  = ((lid >> 3) & 1) << 3;

    uint32_t qfh[4][4], qfl[4][4];
    #pragma unroll
    for (int ks = 0; ks < 4; ks++) {
        uint32_t off = ((uint32_t)(wid * 16 + rowA) * PADK + ks * 16 + koA) * 2;
        ldsm4(sb + BUF_B + off, qfh[ks]);
        ldsm4(sb + BUF_B + KT_B + off, qfl[ks]);
    }
    __syncthreads();

    float S[16][4], O[8][4];
    float m0 = -1e30f, m1 = -1e30f, l0 = 0.f, l1 = 0.f;
    #pragma unroll
    for (int i = 0; i < 8; i++)
        #pragma unroll
        for (int r = 0; r < 4; r++) O[i][r] = 0.f;

    auto issue = [&](int j) {
        uint32_t b = sb + (uint32_t)(j & 1) * BUF_B;
        int k0 = j * 128;
        #pragma unroll
        for (int i = 0; i < 4; i++) {
            int idx = tid + i * 256;
            int row = idx >> 3, g = idx & 7;
            uint32_t so = (uint32_t)(row * (PADK * 2) + g * 16);
            CP16(b + so, pKh + (size_t)(k0 + row) * HDIM + g * 8);
            CP16(b + KT_B + so, pKl + (size_t)(k0 + row) * HDIM + g * 8);
        }
        #pragma unroll
        for (int i = 0; i < 4; i++) {
            int idx = tid + i * 256;
            int row = idx >> 4, g = idx & 15;
            uint32_t so = (uint32_t)(row * (PADV * 2) + g * 16);
            CP16(b + 2 * KT_B + so, pVh + (size_t)row * SEQ + k0 + g * 8);
            CP16(b + 2 * KT_B + VT_B + so, pVl + (size_t)row * SEQ + k0 + g * 8);
        }
        CP_COMMIT();
    };

    const int gr = lid >> 2, c2 = (lid & 3) * 2;
    const int row0 = q0 + wid * 16 + gr;
    const int row1 = row0 + 8;

    issue(0);
    for (int j = 0; j <= qt; j++) {
        if (j < qt) { issue(j + 1); CP_WAIT(1); }
        else        { CP_WAIT(0); }
        __syncthreads();
        const uint32_t b = sb + (uint32_t)(j & 1) * BUF_B;

        // ---- S = Q K^T (split-3) ----
        #pragma unroll
        for (int ni = 0; ni < 16; ni++)
            #pragma unroll
            for (int r = 0; r < 4; r++) S[ni][r] = 0.f;

        #pragma unroll
        for (int nt = 0; nt < 8; nt++) {
            #pragma unroll
            for (int ks = 0; ks < 4; ks++) {
                uint32_t off = ((uint32_t)(nt * 16 + rowB) * PADK + ks * 16 + koB) * 2;
                uint32_t bh[4], bl[4];
                ldsm4(b + off, bh);
                ldsm4(b + KT_B + off, bl);
                mma16816(S[2 * nt],     qfh[ks], bh[0], bh[1]);
                mma16816(S[2 * nt],     qfh[ks], bl[0], bl[1]);
                mma16816(S[2 * nt],     qfl[ks], bh[0], bh[1]);
                mma16816(S[2 * nt + 1], qfh[ks], bh[2], bh[3]);
                mma16816(S[2 * nt + 1], qfh[ks], bl[2], bl[3]);
                mma16816(S[2 * nt + 1], qfl[ks], bh[2], bh[3]);
            }
        }

        // ---- causal mask (diagonal tile only) ----
        if (j == qt) {
            #pragma unroll
            for (int ni = 0; ni < 16; ni++) {
                int kc = j * 128 + ni * 8 + c2;
                if (kc     > row0) S[ni][0] = -1e30f;
                if (kc + 1 > row0) S[ni][1] = -1e30f;
                if (kc     > row1) S[ni][2] = -1e30f;
                if (kc + 1 > row1) S[ni][3] = -1e30f;
            }
        }

        // ---- online softmax ----
        float mx0 = -1e30f, mx1 = -1e30f;
        #pragma unroll
        for (int ni = 0; ni < 16; ni++) {
            mx0 = fmaxf(mx0, fmaxf(S[ni][0], S[ni][1]));
            mx1 = fmaxf(mx1, fmaxf(S[ni][2], S[ni][3]));
        }
        mx0 = fmaxf(mx0, __shfl_xor_sync(0xffffffffu, mx0, 1));
        mx0 = fmaxf(mx0, __shfl_xor_sync(0xffffffffu, mx0, 2));
        mx1 = fmaxf(mx1, __shfl_xor_sync(0xffffffffu, mx1, 1));
        mx1 = fmaxf(mx1, __shfl_xor_sync(0xffffffffu, mx1, 2));
        float mn0 = fmaxf(m0, mx0), mn1 = fmaxf(m1, mx1);
        float corr0 = __expf(m0 - mn0), corr1 = __expf(m1 - mn1);
        m0 = mn0; m1 = mn1;

        float rs0 = 0.f, rs1 = 0.f;
        #pragma unroll
        for (int ni = 0; ni < 16; ni++) {
            float p0 = __expf(S[ni][0] - mn0);
            float p1 = __expf(S[ni][1] - mn0);
            float p2 = __expf(S[ni][2] - mn1);
            float p3 = __expf(S[ni][3] - mn1);
            S[ni][0] = p0; S[ni][1] = p1; S[ni][2] = p2; S[ni][3] = p3;
            rs0 += p0 + p1;
            rs1 += p2 + p3;
        }
        rs0 += __shfl_xor_sync(0xffffffffu, rs0, 1);
        rs0 += __shfl_xor_sync(0xffffffffu, rs0, 2);
        rs1 += __shfl_xor_sync(0xffffffffu, rs1, 1);
        rs1 += __shfl_xor_sync(0xffffffffu, rs1, 2);
        l0 = l0 * corr0 + rs0;
        l1 = l1 * corr1 + rs1;
        #pragma unroll
        for (int nd = 0; nd < 8; nd++) {
            O[nd][0] *= corr0; O[nd][1] *= corr0;
            O[nd][2] *= corr1; O[nd][3] *= corr1;
        }

        // ---- O += P V (P split hi/lo, V split hi/lo, 3 products) ----
        #pragma unroll
        for (int kt = 0; kt < 8; kt++) {
            uint32_t ah[4], al[4];
            {
                float p00 = S[2 * kt][0],     p01 = S[2 * kt][1];
                float p02 = S[2 * kt][2],     p03 = S[2 * kt][3];
                float p10 = S[2 * kt + 1][0], p11 = S[2 * kt + 1][1];
                float p12 = S[2 * kt + 1][2], p13 = S[2 * kt + 1][3];
                ah[0] = pack_bf16(p00, p01);
                ah[1] = pack_bf16(p02, p03);
                ah[2] = pack_bf16(p10, p11);
                ah[3] = pack_bf16(p12, p13);
                __nv_bfloat162 h0 = *(__nv_bfloat162*)&ah[0];
                __nv_bfloat162 h1 = *(__nv_bfloat162*)&ah[1];
                __nv_bfloat162 h2 = *(__nv_bfloat162*)&ah[2];
                __nv_bfloat162 h3 = *(__nv_bfloat162*)&ah[3];
                al[0] = pack_bf16(p00 - __bfloat162float(h0.x), p01 - __bfloat162float(h0.y));
                al[1] = pack_bf16(p02 - __bfloat162float(h1.x), p03 - __bfloat162float(h1.y));
                al[2] = pack_bf16(p10 - __bfloat162float(h2.x), p11 - __bfloat162float(h2.y));
                al[3] = pack_bf16(p12 - __bfloat162float(h3.x), p13 - __bfloat162float(h3.y));
            }
            #pragma unroll
            for (int nd = 0; nd < 4; nd++) {
                uint32_t off = ((uint32_t)(nd * 16 + rowB) * PADV + kt * 16 + koB) * 2;
                uint32_t vh[4], vl[4];
                ldsm4(b + 2 * KT_B + off, vh);
                ldsm4(b + 2 * KT_B + VT_B + off, vl);
                mma16816(O[2 * nd],     ah, vh[0], vh[1]);
                mma16816(O[2 * nd],     ah, vl[0], vl[1]);
                mma16816(O[2 * nd],     al, vh[0], vh[1]);
                mma16816(O[2 * nd + 1], ah, vh[2], vh[3]);
                mma16816(O[2 * nd + 1], ah, vl[2], vl[3]);
                mma16816(O[2 * nd + 1], al, vh[2], vh[3]);
            }
        }
        __syncthreads();
    }

    // ---- epilogue ----
    float inv0 = 1.f / l0, inv1 = 1.f / l1;
    #pragma unroll
    for (int nd = 0; nd < 8; nd++) {
        int d = h * HDIM + nd * 8 + c2;
        *(float2*)&Y[(size_t)row0 * DMODEL + d] = make_float2(O[nd][0] * inv0, O[nd][1] * inv0);
        *(float2*)&Y[(size_t)row1 * DMODEL + d] = make_float2(O[nd][2] * inv1, O[nd][3] * inv1);
    }
}

// ---------------- launch ----------------
extern "C" void kernel_launch(void* const* d_in, const int* in_sizes, int n_in,
                              void* d_out, int out_size) {
    const float* x      = (const float*)d_in[0];
    const float* w_qkv  = (const float*)d_in[1];
    const float* w_proj = (const float*)d_in[2];
    float* out = (float*)d_out;
    (void)in_sizes; (void)n_in; (void)out_size;

    float *p_q, *p_k, *p_v, *p_y;
    __nv_bfloat16 *p_xh, *p_xl, *p_yh, *p_yl, *p_wqh, *p_wql, *p_wph, *p_wpl;
    __nv_bfloat16 *p_qbh, *p_qbl, *p_kbh, *p_kbl, *p_vth, *p_vtl;
    cudaGetSymbolAddress((void**)&p_q,  g_q);
    cudaGetSymbolAddress((void**)&p_k,  g_k);
    cudaGetSymbolAddress((void**)&p_v,  g_v);
    cudaGetSymbolAddress((void**)&p_y,  g_y);
    cudaGetSymbolAddress((void**)&p_xh, g_xh);
    cudaGetSymbolAddress((void**)&p_xl, g_xl);
    cudaGetSymbolAddress((void**)&p_yh, g_yh);
    cudaGetSymbolAddress((void**)&p_yl, g_yl);
    cudaGetSymbolAddress((void**)&p_wqh, g_wqh);
    cudaGetSymbolAddress((void**)&p_wql, g_wql);
    cudaGetSymbolAddress((void**)&p_wph, g_wph);
    cudaGetSymbolAddress((void**)&p_wpl, g_wpl);
    cudaGetSymbolAddress((void**)&p_qbh, g_qbh);
    cudaGetSymbolAddress((void**)&p_qbl, g_qbl);
    cudaGetSymbolAddress((void**)&p_kbh, g_kbh);
    cudaGetSymbolAddress((void**)&p_kbl, g_kbl);
    cudaGetSymbolAddress((void**)&p_vth, g_vth);
    cudaGetSymbolAddress((void**)&p_vtl, g_vtl);

    cudaFuncSetAttribute(gemm_mma_kernel, cudaFuncAttributeMaxDynamicSharedMemorySize, GEMM_SMEM);
    cudaFuncSetAttribute(attn_mma_kernel, cudaFuncAttributeMaxDynamicSharedMemorySize, ATTN_SMEM);

    // 1. RoPE tables
    rope_table_kernel<<<(SEQ * HALF + 255) / 256, 256>>>();

    // 2. prep: x split, w_qkv transpose+split
    split_kernel<<<(SEQ * DMODEL + 255) / 256, 256>>>(x, p_xh, p_xl, SEQ * DMODEL);
    {
        dim3 grid(3 * DMODEL / 32, DMODEL / 32);
        transpose_split_kernel<<<grid, dim3(32, 8)>>>(w_qkv, p_wqh, p_wql, DMODEL, 3 * DMODEL);
    }

    // 3. QKV projection -> fp32 head-major q/k/v
    {
        dim3 grid(3 * DMODEL / 128, SEQ / 128);
        gemm_mma_kernel<<<grid, 256, GEMM_SMEM>>>(p_xh, p_xl, p_wqh, p_wql,
                                                  nullptr, p_q, p_k, p_v,
                                                  3 * DMODEL, DMODEL, 1);
    }

    // 4. RoPE + bf16 split + V transpose
    {
        dim3 grid(SEQ / 64, NHEAD);
        rope_split_kernel<<<grid, 256>>>();
    }

    // 5. flash attention on tensor cores
    {
        dim3 grid(SEQ / 128, NHEAD);
        attn_mma_kernel<<<grid, 256, ATTN_SMEM>>>(p_qbh, p_qbl, p_kbh, p_kbl,
                                                  p_vth, p_vtl, p_y);
    }

    // 6. output projection
    split_kernel<<<(SEQ * DMODEL + 255) / 256, 256>>>(p_y, p_yh, p_yl, SEQ * DMODEL);
    {
        dim3 grid(DMODEL / 32, DMODEL / 32);
        transpose_split_kernel<<<grid, dim3(32, 8)>>>(w_proj, p_wph, p_wpl, DMODEL, DMODEL);
    }
    {
        dim3 grid(DMODEL / 128, SEQ / 128);
        gemm_mma_kernel<<<grid, 256, GEMM_SMEM>>>(p_yh, p_yl, p_wph, p_wpl,
                                                  out, nullptr, nullptr, nullptr,
                                                  DMODEL, DMODEL, 0);
    }
}

// round 8
// speedup vs baseline: 4.8835x; 1.1892x over previous
#include <cuda_runtime.h>
#include <cuda_bf16.h>
#include <cuda_fp16.h>
#include <math.h>
#include <stdint.h>

// Problem constants
#define SEQ    4096
#define DMODEL 1024
#define NHEAD  16
#define HDIM   64
#define HALF   32   // HDIM/2

// ---------------- scratch (device globals) ----------------
__device__ float g_q[(size_t)NHEAD * SEQ * HDIM];   // [h][t][d] fp32 (pre-RoPE)
__device__ float g_k[(size_t)NHEAD * SEQ * HDIM];
__device__ float g_v[(size_t)NHEAD * SEQ * HDIM];
__device__ float g_y[(size_t)SEQ * DMODEL];         // [t][h*64+d]
__device__ float g_cos[SEQ * HALF];
__device__ float g_sin[SEQ * HALF];

// bf16 split operands for projections (split-3, validated)
__device__ __nv_bfloat16 g_xh[(size_t)SEQ * DMODEL];
__device__ __nv_bfloat16 g_xl[(size_t)SEQ * DMODEL];
__device__ __nv_bfloat16 g_yh[(size_t)SEQ * DMODEL];
__device__ __nv_bfloat16 g_yl[(size_t)SEQ * DMODEL];
__device__ __nv_bfloat16 g_wqh[(size_t)3 * DMODEL * DMODEL];
__device__ __nv_bfloat16 g_wql[(size_t)3 * DMODEL * DMODEL];
__device__ __nv_bfloat16 g_wph[(size_t)DMODEL * DMODEL];
__device__ __nv_bfloat16 g_wpl[(size_t)DMODEL * DMODEL];

// fp16 operands for attention (RoPE'd; q pre-scaled by 1/8, split-2; k single; v^T split-2)
__device__ __half g_qfh[(size_t)NHEAD * SEQ * HDIM];   // [h][t][d] hi
__device__ __half g_qfl[(size_t)NHEAD * SEQ * HDIM];   //            lo
__device__ __half g_kf [(size_t)NHEAD * SEQ * HDIM];   // [h][t][d] single
__device__ __half g_vfh[(size_t)NHEAD * HDIM * SEQ];   // [h][d][t] hi (V^T)
__device__ __half g_vfl[(size_t)NHEAD * HDIM * SEQ];   //            lo

// ---------------- helpers ----------------
__device__ __forceinline__ uint32_t smem_to_u32(const void* p) {
    uint32_t a;
    asm("{ .reg .u64 t; cvta.to.shared.u64 t, %1; cvt.u32.u64 %0, t; }" : "=r"(a) : "l"(p));
    return a;
}
__device__ __forceinline__ void ldsm4(uint32_t addr, uint32_t r[4]) {
    asm volatile("ldmatrix.sync.aligned.m8n8.x4.shared.b16 {%0,%1,%2,%3}, [%4];"
                 : "=r"(r[0]), "=r"(r[1]), "=r"(r[2]), "=r"(r[3]) : "r"(addr));
}
__device__ __forceinline__ void mma16816(float c[4], const uint32_t a[4], uint32_t b0, uint32_t b1) {
    asm volatile("mma.sync.aligned.m16n8k16.row.col.f32.bf16.bf16.f32 "
                 "{%0,%1,%2,%3}, {%4,%5,%6,%7}, {%8,%9}, {%0,%1,%2,%3};"
                 : "+f"(c[0]), "+f"(c[1]), "+f"(c[2]), "+f"(c[3])
                 : "r"(a[0]), "r"(a[1]), "r"(a[2]), "r"(a[3]), "r"(b0), "r"(b1));
}
__device__ __forceinline__ void mma16816h(float c[4], const uint32_t a[4], uint32_t b0, uint32_t b1) {
    asm volatile("mma.sync.aligned.m16n8k16.row.col.f32.f16.f16.f32 "
                 "{%0,%1,%2,%3}, {%4,%5,%6,%7}, {%8,%9}, {%0,%1,%2,%3};"
                 : "+f"(c[0]), "+f"(c[1]), "+f"(c[2]), "+f"(c[3])
                 : "r"(a[0]), "r"(a[1]), "r"(a[2]), "r"(a[3]), "r"(b0), "r"(b1));
}
#define CP16(dst, src) \
    asm volatile("cp.async.ca.shared.global [%0], [%1], 16;" :: "r"(dst), "l"(__cvta_generic_to_global(src)))
#define CP_COMMIT() asm volatile("cp.async.commit_group;")
#define CP_WAIT(N)  asm volatile("cp.async.wait_group %0;" :: "n"(N))

__device__ __forceinline__ uint32_t pack_h(float a, float b) {
    __half2 h = __floats2half2_rn(a, b);
    return *(uint32_t*)&h;
}

// ---------------- RoPE cos/sin table ----------------
__global__ void rope_table_kernel() {
    int idx = blockIdx.x * blockDim.x + threadIdx.x;
    if (idx >= SEQ * HALF) return;
    int d = idx & (HALF - 1);
    int t = idx >> 5;
    double inv = exp(-log(10000.0) * (double)d / (double)HALF);
    float invf = (float)inv;
    float f = (float)t * invf;
    g_cos[idx] = (float)cos((double)f);
    g_sin[idx] = (float)sin((double)f);
}

// ---------------- RoPE + fp16 split + V transpose ----------------
__global__ __launch_bounds__(256) void rope_split_kernel() {
    __shared__ float vs[64][65];
    const int h = blockIdx.y, t0 = blockIdx.x * 64;
    const int tid = threadIdx.x;
    const size_t base_ht = ((size_t)h * SEQ + t0) * HDIM;

    #pragma unroll
    for (int i = 0; i < 8; i++) {
        int p = tid + i * 256;             // 2048 pairs
        int tl = p >> 5, d = p & 31;
        int t = t0 + tl;
        float c = g_cos[t * HALF + d], s = g_sin[t * HALF + d];
        size_t b = base_ht + (size_t)tl * HDIM;
        float q1 = g_q[b + d], q2 = g_q[b + d + HALF];
        float r1 = (q1 * c - q2 * s) * 0.125f;
        float r2 = (q2 * c + q1 * s) * 0.125f;
        __half h1 = __float2half_rn(r1);
        __half h2 = __float2half_rn(r2);
        g_qfh[b + d] = h1;        g_qfl[b + d] = __float2half_rn(r1 - __half2float(h1));
        g_qfh[b + d + HALF] = h2; g_qfl[b + d + HALF] = __float2half_rn(r2 - __half2float(h2));
        float k1 = g_k[b + d], k2 = g_k[b + d + HALF];
        g_kf[b + d]        = __float2half_rn(k1 * c - k2 * s);
        g_kf[b + d + HALF] = __float2half_rn(k2 * c + k1 * s);
    }

    // V transpose + split
    #pragma unroll
    for (int i = 0; i < 16; i++) {
        int idx = tid + i * 256;           // 4096
        int tl = idx >> 6, d = idx & 63;
        vs[tl][d] = g_v[base_ht + (size_t)tl * HDIM + d];
    }
    __syncthreads();
    #pragma unroll
    for (int i = 0; i < 16; i++) {
        int idx = tid + i * 256;
        int d = idx >> 6, tl = idx & 63;
        float v = vs[tl][d];
        __half hv = __float2half_rn(v);
        size_t o = ((size_t)h * HDIM + d) * SEQ + t0 + tl;
        g_vfh[o] = hv;
        g_vfl[o] = __float2half_rn(v - __half2float(hv));
    }
}

// ---------------- fp32 -> bf16 hi/lo split ----------------
__global__ void split_kernel(const float* __restrict__ src, __nv_bfloat16* __restrict__ hi,
                             __nv_bfloat16* __restrict__ lo, int n) {
    int i = blockIdx.x * blockDim.x + threadIdx.x;
    if (i >= n) return;
    float v = src[i];
    __nv_bfloat16 h = __float2bfloat16(v);
    hi[i] = h;
    lo[i] = __float2bfloat16(v - __bfloat162float(h));
}

// ---------------- transpose + split: W[K][N] -> Wt hi/lo [N][K] ----------------
__global__ void transpose_split_kernel(const float* __restrict__ W,
                                       __nv_bfloat16* __restrict__ Th,
                                       __nv_bfloat16* __restrict__ Tl, int K, int N) {
    __shared__ float t[32][33];
    int n0 = blockIdx.x * 32, k0 = blockIdx.y * 32;
    int tx = threadIdx.x, ty = threadIdx.y;
    #pragma unroll
    for (int r = 0; r < 4; r++)
        t[ty + 8 * r][tx] = W[(size_t)(k0 + ty + 8 * r) * N + n0 + tx];
    __syncthreads();
    #pragma unroll
    for (int r = 0; r < 4; r++) {
        float v = t[tx][ty + 8 * r];
        __nv_bfloat16 h = __float2bfloat16(v);
        size_t o = (size_t)(n0 + ty + 8 * r) * K + k0 + tx;
        Th[o] = h;
        Tl[o] = __float2bfloat16(v - __bfloat162float(h));
    }
}

// ---------------- mma.sync bf16 split-3 GEMM (validated round 5) ----------------
#define BKC 32
#define TS 40
#define TILE_ELEMS (128 * TS)
#define TILE_BYTES (TILE_ELEMS * 2)
#define GEMM_SMEM (8 * TILE_BYTES)

__global__ __launch_bounds__(256, 1) void gemm_mma_kernel(
    const __nv_bfloat16* __restrict__ Ah, const __nv_bfloat16* __restrict__ Al,
    const __nv_bfloat16* __restrict__ Bh, const __nv_bfloat16* __restrict__ Bl,
    float* __restrict__ C, float* __restrict__ Q, float* __restrict__ Kp,
    float* __restrict__ V, int N, int K, int mode)
{
    extern __shared__ __nv_bfloat16 sm_g[];
    const int tid = threadIdx.x;
    const int wid = tid >> 5, lid = tid & 31;
    const int brow = blockIdx.y * 128, bcol = blockIdx.x * 128;
    const int wm = wid >> 1, wn = wid & 1;
    const uint32_t smem_base = smem_to_u32(sm_g);

    const __nv_bfloat16* srcs[4] = { Ah, Al, Bh, Bl };

    float acc[2][8][4];
    #pragma unroll
    for (int mi = 0; mi < 2; mi++)
        #pragma unroll
        for (int ni = 0; ni < 8; ni++)
            #pragma unroll
            for (int r = 0; r < 4; r++) acc[mi][ni][r] = 0.f;

    const int rowA = lid & 15;
    const int koA  = (lid >> 4) << 3;
    const int rowB = (lid & 7) + ((lid >> 4) << 3);
    const int koB  = ((lid >> 3) & 1) << 3;

    float4 pre[8];

    auto load_regs = [&](int c) {
        #pragma unroll
        for (int t = 0; t < 4; t++) {
            const __nv_bfloat16* s = srcs[t];
            const int rb = (t < 2) ? brow : bcol;
            #pragma unroll
            for (int j = 0; j < 2; j++) {
                int idx = tid + j * 256;
                int row = idx >> 2, g = idx & 3;
                pre[t * 2 + j] = *(const float4*)(s + (size_t)(rb + row) * K + c * BKC + g * 8);
            }
        }
    };
    auto store_smem = [&](int b) {
        #pragma unroll
        for (int t = 0; t < 4; t++) {
            __nv_bfloat16* d = sm_g + (b * 4 + t) * TILE_ELEMS;
            #pragma unroll
            for (int j = 0; j < 2; j++) {
                int idx = tid + j * 256;
                int row = idx >> 2, g = idx & 3;
                *(float4*)(d + row * TS + g * 8) = pre[t * 2 + j];
            }
        }
    };
    auto compute = [&](int b) {
        const uint32_t bA_h = smem_base + (uint32_t)(b * 4 + 0) * TILE_BYTES;
        const uint32_t bA_l = smem_base + (uint32_t)(b * 4 + 1) * TILE_BYTES;
        const uint32_t bB_h = smem_base + (uint32_t)(b * 4 + 2) * TILE_BYTES;
        const uint32_t bB_l = smem_base + (uint32_t)(b * 4 + 3) * TILE_BYTES;
        #pragma unroll
        for (int ks = 0; ks < 2; ks++) {
            uint32_t ah[2][4], al[2][4];
            #pragma unroll
            for (int mi = 0; mi < 2; mi++) {
                uint32_t off = ((uint32_t)(wm * 32 + mi * 16 + rowA) * TS + ks * 16 + koA) * 2;
                ldsm4(bA_h + off, ah[mi]);
                ldsm4(bA_l + off, al[mi]);
            }
            #pragma unroll
            for (int ni2 = 0; ni2 < 4; ni2++) {
                uint32_t off = ((uint32_t)(wn * 64 + ni2 * 16 + rowB) * TS + ks * 16 + koB) * 2;
                uint32_t bh[4], bl[4];
                ldsm4(bB_h + off, bh);
                ldsm4(bB_l + off, bl);
                #pragma unroll
                for (int half = 0; half < 2; half++) {
                    const int ni = ni2 * 2 + half;
                    const uint32_t bh0 = bh[half * 2], bh1 = bh[half * 2 + 1];
                    const uint32_t bl0 = bl[half * 2], bl1 = bl[half * 2 + 1];
                    #pragma unroll
                    for (int mi = 0; mi < 2; mi++) {
                        mma16816(acc[mi][ni], ah[mi], bh0, bh1);
                        mma16816(acc[mi][ni], ah[mi], bl0, bl1);
                        mma16816(acc[mi][ni], al[mi], bh0, bh1);
                    }
                }
            }
        }
    };

    const int nc = K / BKC;
    load_regs(0);
    store_smem(0);
    for (int c = 0; c < nc; c++) {
        __syncthreads();
        if (c + 1 < nc) load_regs(c + 1);
        compute(c & 1);
        if (c + 1 < nc) store_smem((c + 1) & 1);
    }

    #pragma unroll
    for (int mi = 0; mi < 2; mi++) {
        #pragma unroll
        for (int ni = 0; ni < 8; ni++) {
            int row0 = brow + wm * 32 + mi * 16 + (lid >> 2);
            int col  = bcol + wn * 64 + ni * 8 + (lid & 3) * 2;
            if (mode == 1) {
                int sect = col >> 10, nn = col & 1023, h = nn >> 6, d = nn & 63;
                float* dst = (sect == 0) ? Q : (sect == 1) ? Kp : V;
                *(float2*)&dst[((size_t)h * SEQ + row0) * HDIM + d] =
                    make_float2(acc[mi][ni][0], acc[mi][ni][1]);
                *(float2*)&dst[((size_t)h * SEQ + row0 + 8) * HDIM + d] =
                    make_float2(acc[mi][ni][2], acc[mi][ni][3]);
            } else {
                *(float2*)&C[(size_t)row0 * N + col] =
                    make_float2(acc[mi][ni][0], acc[mi][ni][1]);
                *(float2*)&C[(size_t)(row0 + 8) * N + col] =
                    make_float2(acc[mi][ni][2], acc[mi][ni][3]);
            }
        }
    }
}

// ---------------- Flash attention via mma.sync (fp16 split-2, causal) ----------------
// Block per (q-tile 128, head); qt reversed for longest-first scheduling.
#define PADK 72                         // K/Q tile row pitch (fp16 elems)
#define PADV 136                        // V^T tile row pitch
#define KT_B (128 * PADK * 2)           // 18432 B
#define VT_B (64 * PADV * 2)            // 17408 B
#define BUF_B (KT_B + 2 * VT_B)         // 53248 B (K single + V hi/lo)
#define ATTN_SMEM (2 * BUF_B)           // 106496 B

__global__ __launch_bounds__(256, 1) void attn_mma_kernel(
    const __half* __restrict__ Qfh, const __half* __restrict__ Qfl,
    const __half* __restrict__ Kf,
    const __half* __restrict__ Vfh, const __half* __restrict__ Vfl,
    float* __restrict__ Y)
{
    extern __shared__ char asmem[];
    const uint32_t sb = smem_to_u32(asmem);
    const int tid = threadIdx.x;
    const int wid = tid >> 5, lid = tid & 31;
    const int h = blockIdx.y;
    const int qt = gridDim.x - 1 - blockIdx.x;      // longest-first
    const int q0 = qt * 128;

    const __half* pQh = Qfh + (size_t)h * SEQ * HDIM;
    const __half* pQl = Qfl + (size_t)h * SEQ * HDIM;
    const __half* pK  = Kf  + (size_t)h * SEQ * HDIM;
    const __half* pVh = Vfh + (size_t)h * HDIM * SEQ;
    const __half* pVl = Vfl + (size_t)h * HDIM * SEQ;

    // --- stage Q tile (hi/lo) into buf1, ldmatrix to registers ---
    #pragma unroll
    for (int i = 0; i < 4; i++) {
        int idx = tid + i * 256;              // 1024 float4 slots
        int row = idx >> 3, g = idx & 7;
        *(float4*)(asmem + BUF_B + row * (PADK * 2) + g * 16) =
            *(const float4*)(pQh + (size_t)(q0 + row) * HDIM + g * 8);
        *(float4*)(asmem + BUF_B + KT_B + row * (PADK * 2) + g * 16) =
            *(const float4*)(pQl + (size_t)(q0 + row) * HDIM + g * 8);
    }
    __syncthreads();

    const int rowA = lid & 15;
    const int koA  = (lid >> 4) << 3;
    const int rowB = (lid & 7) + ((lid >> 4) << 3);
    const int koB  = ((lid >> 3) & 1) << 3;

    uint32_t qfh[4][4], qfl[4][4];
    #pragma unroll
    for (int ks = 0; ks < 4; ks++) {
        uint32_t off = ((uint32_t)(wid * 16 + rowA) * PADK + ks * 16 + koA) * 2;
        ldsm4(sb + BUF_B + off, qfh[ks]);
        ldsm4(sb + BUF_B + KT_B + off, qfl[ks]);
    }
    __syncthreads();

    float S[16][4], O[8][4];
    float m0 = -1e30f, m1 = -1e30f, l0 = 0.f, l1 = 0.f;
    #pragma unroll
    for (int i = 0; i < 8; i++)
        #pragma unroll
        for (int r = 0; r < 4; r++) O[i][r] = 0.f;

    auto issue = [&](int j) {
        uint32_t b = sb + (uint32_t)(j & 1) * BUF_B;
        int k0 = j * 128;
        #pragma unroll
        for (int i = 0; i < 4; i++) {
            int idx = tid + i * 256;
            int row = idx >> 3, g = idx & 7;
            CP16(b + (uint32_t)(row * (PADK * 2) + g * 16),
                 pK + (size_t)(k0 + row) * HDIM + g * 8);
        }
        #pragma unroll
        for (int i = 0; i < 4; i++) {
            int idx = tid + i * 256;
            int row = idx >> 4, g = idx & 15;
            uint32_t so = (uint32_t)(row * (PADV * 2) + g * 16);
            CP16(b + KT_B + so, pVh + (size_t)row * SEQ + k0 + g * 8);
            CP16(b + KT_B + VT_B + so, pVl + (size_t)row * SEQ + k0 + g * 8);
        }
        CP_COMMIT();
    };

    const int gr = lid >> 2, c2 = (lid & 3) * 2;
    const int row0 = q0 + wid * 16 + gr;
    const int row1 = row0 + 8;

    issue(0);
    for (int j = 0; j <= qt; j++) {
        if (j < qt) { issue(j + 1); CP_WAIT(1); }
        else        { CP_WAIT(0); }
        __syncthreads();
        const uint32_t b = sb + (uint32_t)(j & 1) * BUF_B;

        // ---- S = Q K^T (Q split-2, K single) ----
        #pragma unroll
        for (int ni = 0; ni < 16; ni++)
            #pragma unroll
            for (int r = 0; r < 4; r++) S[ni][r] = 0.f;

        #pragma unroll
        for (int nt = 0; nt < 8; nt++) {
            #pragma unroll
            for (int ks = 0; ks < 4; ks++) {
                uint32_t off = ((uint32_t)(nt * 16 + rowB) * PADK + ks * 16 + koB) * 2;
                uint32_t bh[4];
                ldsm4(b + off, bh);
                mma16816h(S[2 * nt],     qfh[ks], bh[0], bh[1]);
                mma16816h(S[2 * nt],     qfl[ks], bh[0], bh[1]);
                mma16816h(S[2 * nt + 1], qfh[ks], bh[2], bh[3]);
                mma16816h(S[2 * nt + 1], qfl[ks], bh[2], bh[3]);
            }
        }

        // ---- causal mask (diagonal tile only) ----
        if (j == qt) {
            #pragma unroll
            for (int ni = 0; ni < 16; ni++) {
                int kc = j * 128 + ni * 8 + c2;
                if (kc     > row0) S[ni][0] = -1e30f;
                if (kc + 1 > row0) S[ni][1] = -1e30f;
                if (kc     > row1) S[ni][2] = -1e30f;
                if (kc + 1 > row1) S[ni][3] = -1e30f;
            }
        }

        // ---- online softmax ----
        float mx0 = -1e30f, mx1 = -1e30f;
        #pragma unroll
        for (int ni = 0; ni < 16; ni++) {
            mx0 = fmaxf(mx0, fmaxf(S[ni][0], S[ni][1]));
            mx1 = fmaxf(mx1, fmaxf(S[ni][2], S[ni][3]));
        }
        mx0 = fmaxf(mx0, __shfl_xor_sync(0xffffffffu, mx0, 1));
        mx0 = fmaxf(mx0, __shfl_xor_sync(0xffffffffu, mx0, 2));
        mx1 = fmaxf(mx1, __shfl_xor_sync(0xffffffffu, mx1, 1));
        mx1 = fmaxf(mx1, __shfl_xor_sync(0xffffffffu, mx1, 2));
        float mn0 = fmaxf(m0, mx0), mn1 = fmaxf(m1, mx1);
        float corr0 = __expf(m0 - mn0), corr1 = __expf(m1 - mn1);
        m0 = mn0; m1 = mn1;

        float rs0 = 0.f, rs1 = 0.f;
        #pragma unroll
        for (int ni = 0; ni < 16; ni++) {
            float p0 = __expf(S[ni][0] - mn0);
            float p1 = __expf(S[ni][1] - mn0);
            float p2 = __expf(S[ni][2] - mn1);
            float p3 = __expf(S[ni][3] - mn1);
            S[ni][0] = p0; S[ni][1] = p1; S[ni][2] = p2; S[ni][3] = p3;
            rs0 += p0 + p1;
            rs1 += p2 + p3;
        }
        rs0 += __shfl_xor_sync(0xffffffffu, rs0, 1);
        rs0 += __shfl_xor_sync(0xffffffffu, rs0, 2);
        rs1 += __shfl_xor_sync(0xffffffffu, rs1, 1);
        rs1 += __shfl_xor_sync(0xffffffffu, rs1, 2);
        l0 = l0 * corr0 + rs0;
        l1 = l1 * corr1 + rs1;
        #pragma unroll
        for (int nd = 0; nd < 8; nd++) {
            O[nd][0] *= corr0; O[nd][1] *= corr0;
            O[nd][2] *= corr1; O[nd][3] *= corr1;
        }

        // ---- O += P V (P single fp16, V split-2) ----
        #pragma unroll
        for (int kt = 0; kt < 8; kt++) {
            uint32_t a[4];
            a[0] = pack_h(S[2 * kt][0],     S[2 * kt][1]);
            a[1] = pack_h(S[2 * kt][2],     S[2 * kt][3]);
            a[2] = pack_h(S[2 * kt + 1][0], S[2 * kt + 1][1]);
            a[3] = pack_h(S[2 * kt + 1][2], S[2 * kt + 1][3]);
            #pragma unroll
            for (int nd = 0; nd < 4; nd++) {
                uint32_t off = ((uint32_t)(nd * 16 + rowB) * PADV + kt * 16 + koB) * 2;
                uint32_t vh[4], vl[4];
                ldsm4(b + KT_B + off, vh);
                ldsm4(b + KT_B + VT_B + off, vl);
                mma16816h(O[2 * nd],     a, vh[0], vh[1]);
                mma16816h(O[2 * nd],     a, vl[0], vl[1]);
                mma16816h(O[2 * nd + 1], a, vh[2], vh[3]);
                mma16816h(O[2 * nd + 1], a, vl[2], vl[3]);
            }
        }
        __syncthreads();
    }

    // ---- epilogue ----
    float inv0 = 1.f / l0, inv1 = 1.f / l1;
    #pragma unroll
    for (int nd = 0; nd < 8; nd++) {
        int d = h * HDIM + nd * 8 + c2;
        *(float2*)&Y[(size_t)row0 * DMODEL + d] = make_float2(O[nd][0] * inv0, O[nd][1] * inv0);
        *(float2*)&Y[(size_t)row1 * DMODEL + d] = make_float2(O[nd][2] * inv1, O[nd][3] * inv1);
    }
}

// ---------------- launch ----------------
extern "C" void kernel_launch(void* const* d_in, const int* in_sizes, int n_in,
                              void* d_out, int out_size) {
    const float* x      = (const float*)d_in[0];
    const float* w_qkv  = (const float*)d_in[1];
    const float* w_proj = (const float*)d_in[2];
    float* out = (float*)d_out;
    (void)in_sizes; (void)n_in; (void)out_size;

    float *p_q, *p_k, *p_v, *p_y;
    __nv_bfloat16 *p_xh, *p_xl, *p_yh, *p_yl, *p_wqh, *p_wql, *p_wph, *p_wpl;
    __half *p_qfh, *p_qfl, *p_kf, *p_vfh, *p_vfl;
    cudaGetSymbolAddress((void**)&p_q,  g_q);
    cudaGetSymbolAddress((void**)&p_k,  g_k);
    cudaGetSymbolAddress((void**)&p_v,  g_v);
    cudaGetSymbolAddress((void**)&p_y,  g_y);
    cudaGetSymbolAddress((void**)&p_xh, g_xh);
    cudaGetSymbolAddress((void**)&p_xl, g_xl);
    cudaGetSymbolAddress((void**)&p_yh, g_yh);
    cudaGetSymbolAddress((void**)&p_yl, g_yl);
    cudaGetSymbolAddress((void**)&p_wqh, g_wqh);
    cudaGetSymbolAddress((void**)&p_wql, g_wql);
    cudaGetSymbolAddress((void**)&p_wph, g_wph);
    cudaGetSymbolAddress((void**)&p_wpl, g_wpl);
    cudaGetSymbolAddress((void**)&p_qfh, g_qfh);
    cudaGetSymbolAddress((void**)&p_qfl, g_qfl);
    cudaGetSymbolAddress((void**)&p_kf,  g_kf);
    cudaGetSymbolAddress((void**)&p_vfh, g_vfh);
    cudaGetSymbolAddress((void**)&p_vfl, g_vfl);

    cudaFuncSetAttribute(gemm_mma_kernel, cudaFuncAttributeMaxDynamicSharedMemorySize, GEMM_SMEM);
    cudaFuncSetAttribute(attn_mma_kernel, cudaFuncAttributeMaxDynamicSharedMemorySize, ATTN_SMEM);

    // 1. RoPE tables
    rope_table_kernel<<<(SEQ * HALF + 255) / 256, 256>>>();

    // 2. prep: x split, w_qkv transpose+split
    split_kernel<<<(SEQ * DMODEL + 255) / 256, 256>>>(x, p_xh, p_xl, SEQ * DMODEL);
    {
        dim3 grid(3 * DMODEL / 32, DMODEL / 32);
        transpose_split_kernel<<<grid, dim3(32, 8)>>>(w_qkv, p_wqh, p_wql, DMODEL, 3 * DMODEL);
    }

    // 3. QKV projection -> fp32 head-major q/k/v
    {
        dim3 grid(3 * DMODEL / 128, SEQ / 128);
        gemm_mma_kernel<<<grid, 256, GEMM_SMEM>>>(p_xh, p_xl, p_wqh, p_wql,
                                                  nullptr, p_q, p_k, p_v,
                                                  3 * DMODEL, DMODEL, 1);
    }

    // 4. RoPE + fp16 split + V transpose
    {
        dim3 grid(SEQ / 64, NHEAD);
        rope_split_kernel<<<grid, 256>>>();
    }

    // 5. flash attention on tensor cores
    {
        dim3 grid(SEQ / 128, NHEAD);
        attn_mma_kernel<<<grid, 256, ATTN_SMEM>>>(p_qfh, p_qfl, p_kf, p_vfh, p_vfl, p_y);
    }

    // 6. output projection
    split_kernel<<<(SEQ * DMODEL + 255) / 256, 256>>>(p_y, p_yh, p_yl, SEQ * DMODEL);
    {
        dim3 grid(DMODEL / 32, DMODEL / 32);
        transpose_split_kernel<<<grid, dim3(32, 8)>>>(w_proj, p_wph, p_wpl, DMODEL, DMODEL);
    }
    {
        dim3 grid(DMODEL / 128, SEQ / 128);
        gemm_mma_kernel<<<grid, 256, GEMM_SMEM>>>(p_yh, p_yl, p_wph, p_wpl,
                                                  out, nullptr, nullptr, nullptr,
                                                  DMODEL, DMODEL, 0);
    }
}

// round 9
// speedup vs baseline: 5.8867x; 1.2054x over previous
#include <cuda_runtime.h>
#include <cuda_bf16.h>
#include <cuda_fp16.h>
#include <math.h>
#include <stdint.h>

// Problem constants
#define SEQ    4096
#define DMODEL 1024
#define NHEAD  16
#define HDIM   64
#define HALF   32   // HDIM/2

// ---------------- scratch (device globals) ----------------
__device__ float g_v[(size_t)NHEAD * SEQ * HDIM];   // [h][t][d] fp32
__device__ float g_y[(size_t)SEQ * DMODEL];         // [t][h*64+d]
__device__ float g_cos[SEQ * HALF];
__device__ float g_sin[SEQ * HALF];

// fp16 split operands for projections
__device__ __half g_xh[(size_t)SEQ * DMODEL];
__device__ __half g_xl[(size_t)SEQ * DMODEL];
__device__ __half g_yh[(size_t)SEQ * DMODEL];
__device__ __half g_yl[(size_t)SEQ * DMODEL];
__device__ __half g_wq[(size_t)3 * DMODEL * DMODEL];  // w_qkv^T [3072][1024] fp16
__device__ __half g_wp[(size_t)DMODEL * DMODEL];      // w_proj^T [1024][1024] fp16

// fp16 operands for attention (RoPE'd; q pre-scaled by 1/8, split-2; k single; v^T split-2)
__device__ __half g_qfh[(size_t)NHEAD * SEQ * HDIM];   // [h][t][d] hi
__device__ __half g_qfl[(size_t)NHEAD * SEQ * HDIM];   //            lo
__device__ __half g_kf [(size_t)NHEAD * SEQ * HDIM];   // [h][t][d] single
__device__ __half g_vfh[(size_t)NHEAD * HDIM * SEQ];   // [h][d][t] hi (V^T)
__device__ __half g_vfl[(size_t)NHEAD * HDIM * SEQ];   //            lo

// ---------------- helpers ----------------
__device__ __forceinline__ uint32_t smem_to_u32(const void* p) {
    uint32_t a;
    asm("{ .reg .u64 t; cvta.to.shared.u64 t, %1; cvt.u32.u64 %0, t; }" : "=r"(a) : "l"(p));
    return a;
}
__device__ __forceinline__ void ldsm4(uint32_t addr, uint32_t r[4]) {
    asm volatile("ldmatrix.sync.aligned.m8n8.x4.shared.b16 {%0,%1,%2,%3}, [%4];"
                 : "=r"(r[0]), "=r"(r[1]), "=r"(r[2]), "=r"(r[3]) : "r"(addr));
}
__device__ __forceinline__ void mma16816h(float c[4], const uint32_t a[4], uint32_t b0, uint32_t b1) {
    asm volatile("mma.sync.aligned.m16n8k16.row.col.f32.f16.f16.f32 "
                 "{%0,%1,%2,%3}, {%4,%5,%6,%7}, {%8,%9}, {%0,%1,%2,%3};"
                 : "+f"(c[0]), "+f"(c[1]), "+f"(c[2]), "+f"(c[3])
                 : "r"(a[0]), "r"(a[1]), "r"(a[2]), "r"(a[3]), "r"(b0), "r"(b1));
}
#define CP16(dst, src) \
    asm volatile("cp.async.ca.shared.global [%0], [%1], 16;" :: "r"(dst), "l"(__cvta_generic_to_global(src)))
#define CP_COMMIT() asm volatile("cp.async.commit_group;")
#define CP_WAIT(N)  asm volatile("cp.async.wait_group %0;" :: "n"(N))

__device__ __forceinline__ uint32_t pack_h(float a, float b) {
    __half2 h = __floats2half2_rn(a, b);
    return *(uint32_t*)&h;
}

// ---------------- RoPE cos/sin table ----------------
__global__ void rope_table_kernel() {
    int idx = blockIdx.x * blockDim.x + threadIdx.x;
    if (idx >= SEQ * HALF) return;
    int d = idx & (HALF - 1);
    int t = idx >> 5;
    double inv = exp(-log(10000.0) * (double)d / (double)HALF);
    float invf = (float)inv;
    float f = (float)t * invf;
    g_cos[idx] = (float)cos((double)f);
    g_sin[idx] = (float)sin((double)f);
}

// ---------------- fp32 -> fp16 hi/lo split ----------------
__global__ void split_half_kernel(const float* __restrict__ src, __half* __restrict__ hi,
                                  __half* __restrict__ lo, int n) {
    int i = blockIdx.x * blockDim.x + threadIdx.x;
    if (i >= n) return;
    float v = src[i];
    __half h = __float2half_rn(v);
    hi[i] = h;
    lo[i] = __float2half_rn(v - __half2float(h));
}

// ---------------- transpose + fp16: W[K][N] -> Wt [N][K] ----------------
__global__ void transpose_half_kernel(const float* __restrict__ W,
                                      __half* __restrict__ T, int K, int N) {
    __shared__ float t[32][33];
    int n0 = blockIdx.x * 32, k0 = blockIdx.y * 32;
    int tx = threadIdx.x, ty = threadIdx.y;
    #pragma unroll
    for (int r = 0; r < 4; r++)
        t[ty + 8 * r][tx] = W[(size_t)(k0 + ty + 8 * r) * N + n0 + tx];
    __syncthreads();
    #pragma unroll
    for (int r = 0; r < 4; r++)
        T[(size_t)(n0 + ty + 8 * r) * K + k0 + tx] = __float2half_rn(t[tx][ty + 8 * r]);
}

// ---------------- V transpose + split: g_v [h][t][d] -> vfh/vfl [h][d][t] ----------------
__global__ __launch_bounds__(256) void vsplit_kernel() {
    __shared__ float vs[64][65];
    const int h = blockIdx.y, t0 = blockIdx.x * 64;
    const int tid = threadIdx.x;
    const size_t base_ht = ((size_t)h * SEQ + t0) * HDIM;
    #pragma unroll
    for (int i = 0; i < 16; i++) {
        int idx = tid + i * 256;
        int tl = idx >> 6, d = idx & 63;
        vs[tl][d] = g_v[base_ht + (size_t)tl * HDIM + d];
    }
    __syncthreads();
    #pragma unroll
    for (int i = 0; i < 16; i++) {
        int idx = tid + i * 256;
        int d = idx >> 6, tl = idx & 63;
        float v = vs[tl][d];
        __half hv = __float2half_rn(v);
        size_t o = ((size_t)h * HDIM + d) * SEQ + t0 + tl;
        g_vfh[o] = hv;
        g_vfl[o] = __float2half_rn(v - __half2float(hv));
    }
}

// ---------------- mma.sync fp16 split-2 GEMM ----------------
// C = A @ B; A fp16 hi/lo [M][K]; B fp16 single, transposed [N][K].
// CTA 128x128, BK=32, 8 warps, warp tile 32x64, double-buffered smem.
// mode 1: fused RoPE epilogue -> q/k fp16 (+split) and v fp32.  mode 0: fp32 C.
#define BKC 32
#define TS 40
#define TILE_ELEMS (128 * TS)
#define TILE_BYTES (TILE_ELEMS * 2)
#define GEMM_SMEM (6 * TILE_BYTES)     // 2 buffers x 3 tiles = 61440 B

__global__ __launch_bounds__(256, 1) void gemm_mma_kernel(
    const __half* __restrict__ Ah, const __half* __restrict__ Al,
    const __half* __restrict__ B,
    float* __restrict__ C, __half* __restrict__ Qh, __half* __restrict__ Ql,
    __half* __restrict__ Kf, float* __restrict__ V, int N, int K, int mode)
{
    extern __shared__ __half sm_g[];
    const int tid = threadIdx.x;
    const int wid = tid >> 5, lid = tid & 31;
    const int brow = blockIdx.y * 128, bcol = blockIdx.x * 128;
    const int wm = wid >> 1, wn = wid & 1;
    const uint32_t smem_base = smem_to_u32(sm_g);

    const __half* srcs[3] = { Ah, Al, B };

    float acc[2][8][4];
    #pragma unroll
    for (int mi = 0; mi < 2; mi++)
        #pragma unroll
        for (int ni = 0; ni < 8; ni++)
            #pragma unroll
            for (int r = 0; r < 4; r++) acc[mi][ni][r] = 0.f;

    const int rowA = lid & 15;
    const int koA  = (lid >> 4) << 3;
    const int rowB = (lid & 7) + ((lid >> 4) << 3);
    const int koB  = ((lid >> 3) & 1) << 3;

    float4 pre[6];

    auto load_regs = [&](int c) {
        #pragma unroll
        for (int t = 0; t < 3; t++) {
            const __half* s = srcs[t];
            const int rb = (t < 2) ? brow : bcol;
            #pragma unroll
            for (int j = 0; j < 2; j++) {
                int idx = tid + j * 256;
                int row = idx >> 2, g = idx & 3;
                pre[t * 2 + j] = *(const float4*)(s + (size_t)(rb + row) * K + c * BKC + g * 8);
            }
        }
    };
    auto store_smem = [&](int b) {
        #pragma unroll
        for (int t = 0; t < 3; t++) {
            __half* d = sm_g + (b * 3 + t) * TILE_ELEMS;
            #pragma unroll
            for (int j = 0; j < 2; j++) {
                int idx = tid + j * 256;
                int row = idx >> 2, g = idx & 3;
                *(float4*)(d + row * TS + g * 8) = pre[t * 2 + j];
            }
        }
    };
    auto compute = [&](int b) {
        const uint32_t bA_h = smem_base + (uint32_t)(b * 3 + 0) * TILE_BYTES;
        const uint32_t bA_l = smem_base + (uint32_t)(b * 3 + 1) * TILE_BYTES;
        const uint32_t bB   = smem_base + (uint32_t)(b * 3 + 2) * TILE_BYTES;
        #pragma unroll
        for (int ks = 0; ks < 2; ks++) {
            uint32_t ah[2][4], al[2][4];
            #pragma unroll
            for (int mi = 0; mi < 2; mi++) {
                uint32_t off = ((uint32_t)(wm * 32 + mi * 16 + rowA) * TS + ks * 16 + koA) * 2;
                ldsm4(bA_h + off, ah[mi]);
                ldsm4(bA_l + off, al[mi]);
            }
            #pragma unroll
            for (int ni2 = 0; ni2 < 4; ni2++) {
                uint32_t off = ((uint32_t)(wn * 64 + ni2 * 16 + rowB) * TS + ks * 16 + koB) * 2;
                uint32_t bh[4];
                ldsm4(bB + off, bh);
                #pragma unroll
                for (int half2i = 0; half2i < 2; half2i++) {
                    const int ni = ni2 * 2 + half2i;
                    const uint32_t b0 = bh[half2i * 2], b1 = bh[half2i * 2 + 1];
                    #pragma unroll
                    for (int mi = 0; mi < 2; mi++) {
                        mma16816h(acc[mi][ni], ah[mi], b0, b1);
                        mma16816h(acc[mi][ni], al[mi], b0, b1);
                    }
                }
            }
        }
    };

    const int nc = K / BKC;
    load_regs(0);
    store_smem(0);
    for (int c = 0; c < nc; c++) {
        __syncthreads();
        if (c + 1 < nc) load_regs(c + 1);
        compute(c & 1);
        if (c + 1 < nc) store_smem((c + 1) & 1);
    }

    const int gr = lid >> 2, c2v = (lid & 3) * 2;
    if (mode == 1) {
        // fused RoPE + fp16 split epilogue.
        // Warp tile is 64 wide == one head; thread holds pair (d, d+32) as (ni, ni+4).
        #pragma unroll
        for (int mi = 0; mi < 2; mi++) {
            int row0 = brow + wm * 32 + mi * 16 + gr;
            int row1 = row0 + 8;
            #pragma unroll
            for (int ni = 0; ni < 4; ni++) {
                int col = bcol + wn * 64 + ni * 8 + c2v;
                int sect = col >> 10;
                int nn = col & 1023;
                int h = nn >> 6, d = nn & 63;      // d < 32
                float* a0 = acc[mi][ni];
                float* a1 = acc[mi][ni + 4];
                size_t b0 = ((size_t)h * SEQ + row0) * HDIM;
                size_t b1 = ((size_t)h * SEQ + row1) * HDIM;
                if (sect == 2) {
                    *(float2*)&V[b0 + d]      = make_float2(a0[0], a0[1]);
                    *(float2*)&V[b1 + d]      = make_float2(a0[2], a0[3]);
                    *(float2*)&V[b0 + d + 32] = make_float2(a1[0], a1[1]);
                    *(float2*)&V[b1 + d + 32] = make_float2(a1[2], a1[3]);
                } else {
                    float2 c0 = *(const float2*)&g_cos[row0 * HALF + d];
                    float2 s0 = *(const float2*)&g_sin[row0 * HALF + d];
                    float2 c1 = *(const float2*)&g_cos[row1 * HALF + d];
                    float2 s1 = *(const float2*)&g_sin[row1 * HALF + d];
                    float e1[4], e2[4];
                    e1[0] = a0[0] * c0.x - a1[0] * s0.x;  e2[0] = a1[0] * c0.x + a0[0] * s0.x;
                    e1[1] = a0[1] * c0.y - a1[1] * s0.y;  e2[1] = a1[1] * c0.y + a0[1] * s0.y;
                    e1[2] = a0[2] * c1.x - a1[2] * s1.x;  e2[2] = a1[2] * c1.x + a0[2] * s1.x;
                    e1[3] = a0[3] * c1.y - a1[3] * s1.y;  e2[3] = a1[3] * c1.y + a0[3] * s1.y;
                    if (sect == 0) {
                        #pragma unroll
                        for (int r = 0; r < 4; r++) { e1[r] *= 0.125f; e2[r] *= 0.125f; }
                        __half2 h10 = __floats2half2_rn(e1[0], e1[1]);
                        __half2 h12 = __floats2half2_rn(e1[2], e1[3]);
                        __half2 h20 = __floats2half2_rn(e2[0], e2[1]);
                        __half2 h22 = __floats2half2_rn(e2[2], e2[3]);
                        *(__half2*)&Qh[b0 + d]      = h10;
                        *(__half2*)&Qh[b1 + d]      = h12;
                        *(__half2*)&Qh[b0 + d + 32] = h20;
                        *(__half2*)&Qh[b1 + d + 32] = h22;
                        *(__half2*)&Ql[b0 + d] =
                            __floats2half2_rn(e1[0] - __low2float(h10), e1[1] - __high2float(h10));
                        *(__half2*)&Ql[b1 + d] =
                            __floats2half2_rn(e1[2] - __low2float(h12), e1[3] - __high2float(h12));
                        *(__half2*)&Ql[b0 + d + 32] =
                            __floats2half2_rn(e2[0] - __low2float(h20), e2[1] - __high2float(h20));
                        *(__half2*)&Ql[b1 + d + 32] =
                            __floats2half2_rn(e2[2] - __low2float(h22), e2[3] - __high2float(h22));
                    } else {
                        *(__half2*)&Kf[b0 + d]      = __floats2half2_rn(e1[0], e1[1]);
                        *(__half2*)&Kf[b1 + d]      = __floats2half2_rn(e1[2], e1[3]);
                        *(__half2*)&Kf[b0 + d + 32] = __floats2half2_rn(e2[0], e2[1]);
                        *(__half2*)&Kf[b1 + d + 32] = __floats2half2_rn(e2[2], e2[3]);
                    }
                }
            }
        }
    } else {
        #pragma unroll
        for (int mi = 0; mi < 2; mi++) {
            #pragma unroll
            for (int ni = 0; ni < 8; ni++) {
                int row0 = brow + wm * 32 + mi * 16 + gr;
                int col  = bcol + wn * 64 + ni * 8 + c2v;
                *(float2*)&C[(size_t)row0 * N + col] =
                    make_float2(acc[mi][ni][0], acc[mi][ni][1]);
                *(float2*)&C[(size_t)(row0 + 8) * N + col] =
                    make_float2(acc[mi][ni][2], acc[mi][ni][3]);
            }
        }
    }
}

// ---------------- Flash attention via mma.sync (fp16 split-2, causal) ----------------
#define PADK 72
#define PADV 136
#define KT_B (128 * PADK * 2)           // 18432 B
#define VT_B (64 * PADV * 2)            // 17408 B
#define BUF_B (KT_B + 2 * VT_B)         // 53248 B
#define ATTN_SMEM (2 * BUF_B)           // 106496 B

__global__ __launch_bounds__(256, 1) void attn_mma_kernel(
    const __half* __restrict__ Qfh, const __half* __restrict__ Qfl,
    const __half* __restrict__ Kf,
    const __half* __restrict__ Vfh, const __half* __restrict__ Vfl,
    float* __restrict__ Y)
{
    extern __shared__ char asmem[];
    const uint32_t sb = smem_to_u32(asmem);
    const int tid = threadIdx.x;
    const int wid = tid >> 5, lid = tid & 31;
    const int h = blockIdx.y;
    const int qt = gridDim.x - 1 - blockIdx.x;      // longest-first
    const int q0 = qt * 128;

    const __half* pQh = Qfh + (size_t)h * SEQ * HDIM;
    const __half* pQl = Qfl + (size_t)h * SEQ * HDIM;
    const __half* pK  = Kf  + (size_t)h * SEQ * HDIM;
    const __half* pVh = Vfh + (size_t)h * HDIM * SEQ;
    const __half* pVl = Vfl + (size_t)h * HDIM * SEQ;

    #pragma unroll
    for (int i = 0; i < 4; i++) {
        int idx = tid + i * 256;
        int row = idx >> 3, g = idx & 7;
        *(float4*)(asmem + BUF_B + row * (PADK * 2) + g * 16) =
            *(const float4*)(pQh + (size_t)(q0 + row) * HDIM + g * 8);
        *(float4*)(asmem + BUF_B + KT_B + row * (PADK * 2) + g * 16) =
            *(const float4*)(pQl + (size_t)(q0 + row) * HDIM + g * 8);
    }
    __syncthreads();

    const int rowA = lid & 15;
    const int koA  = (lid >> 4) << 3;
    const int rowB = (lid & 7) + ((lid >> 4) << 3);
    const int koB  = ((lid >> 3) & 1) << 3;

    uint32_t qfh[4][4], qfl[4][4];
    #pragma unroll
    for (int ks = 0; ks < 4; ks++) {
        uint32_t off = ((uint32_t)(wid * 16 + rowA) * PADK + ks * 16 + koA) * 2;
        ldsm4(sb + BUF_B + off, qfh[ks]);
        ldsm4(sb + BUF_B + KT_B + off, qfl[ks]);
    }
    __syncthreads();

    float S[16][4], O[8][4];
    float m0 = -1e30f, m1 = -1e30f, l0 = 0.f, l1 = 0.f;
    #pragma unroll
    for (int i = 0; i < 8; i++)
        #pragma unroll
        for (int r = 0; r < 4; r++) O[i][r] = 0.f;

    auto issue = [&](int j) {
        uint32_t b = sb + (uint32_t)(j & 1) * BUF_B;
        int k0 = j * 128;
        #pragma unroll
        for (int i = 0; i < 4; i++) {
            int idx = tid + i * 256;
            int row = idx >> 3, g = idx & 7;
            CP16(b + (uint32_t)(row * (PADK * 2) + g * 16),
                 pK + (size_t)(k0 + row) * HDIM + g * 8);
        }
        #pragma unroll
        for (int i = 0; i < 4; i++) {
            int idx = tid + i * 256;
            int row = idx >> 4, g = idx & 15;
            uint32_t so = (uint32_t)(row * (PADV * 2) + g * 16);
            CP16(b + KT_B + so, pVh + (size_t)row * SEQ + k0 + g * 8);
            CP16(b + KT_B + VT_B + so, pVl + (size_t)row * SEQ + k0 + g * 8);
        }
        CP_COMMIT();
    };

    const int gr = lid >> 2, c2 = (lid & 3) * 2;
    const int row0 = q0 + wid * 16 + gr;
    const int row1 = row0 + 8;

    issue(0);
    for (int j = 0; j <= qt; j++) {
        if (j < qt) { issue(j + 1); CP_WAIT(1); }
        else        { CP_WAIT(0); }
        __syncthreads();
        const uint32_t b = sb + (uint32_t)(j & 1) * BUF_B;

        #pragma unroll
        for (int ni = 0; ni < 16; ni++)
            #pragma unroll
            for (int r = 0; r < 4; r++) S[ni][r] = 0.f;

        #pragma unroll
        for (int nt = 0; nt < 8; nt++) {
            #pragma unroll
            for (int ks = 0; ks < 4; ks++) {
                uint32_t off = ((uint32_t)(nt * 16 + rowB) * PADK + ks * 16 + koB) * 2;
                uint32_t bh[4];
                ldsm4(b + off, bh);
                mma16816h(S[2 * nt],     qfh[ks], bh[0], bh[1]);
                mma16816h(S[2 * nt],     qfl[ks], bh[0], bh[1]);
                mma16816h(S[2 * nt + 1], qfh[ks], bh[2], bh[3]);
                mma16816h(S[2 * nt + 1], qfl[ks], bh[2], bh[3]);
            }
        }

        if (j == qt) {
            #pragma unroll
            for (int ni = 0; ni < 16; ni++) {
                int kc = j * 128 + ni * 8 + c2;
                if (kc     > row0) S[ni][0] = -1e30f;
                if (kc + 1 > row0) S[ni][1] = -1e30f;
                if (kc     > row1) S[ni][2] = -1e30f;
                if (kc + 1 > row1) S[ni][3] = -1e30f;
            }
        }

        float mx0 = -1e30f, mx1 = -1e30f;
        #pragma unroll
        for (int ni = 0; ni < 16; ni++) {
            mx0 = fmaxf(mx0, fmaxf(S[ni][0], S[ni][1]));
            mx1 = fmaxf(mx1, fmaxf(S[ni][2], S[ni][3]));
        }
        mx0 = fmaxf(mx0, __shfl_xor_sync(0xffffffffu, mx0, 1));
        mx0 = fmaxf(mx0, __shfl_xor_sync(0xffffffffu, mx0, 2));
        mx1 = fmaxf(mx1, __shfl_xor_sync(0xffffffffu, mx1, 1));
        mx1 = fmaxf(mx1, __shfl_xor_sync(0xffffffffu, mx1, 2));
        float mn0 = fmaxf(m0, mx0), mn1 = fmaxf(m1, mx1);
        float corr0 = __expf(m0 - mn0), corr1 = __expf(m1 - mn1);
        m0 = mn0; m1 = mn1;

        float rs0 = 0.f, rs1 = 0.f;
        #pragma unroll
        for (int ni = 0; ni < 16; ni++) {
            float p0 = __expf(S[ni][0] - mn0);
            float p1 = __expf(S[ni][1] - mn0);
            float p2 = __expf(S[ni][2] - mn1);
            float p3 = __expf(S[ni][3] - mn1);
            S[ni][0] = p0; S[ni][1] = p1; S[ni][2] = p2; S[ni][3] = p3;
            rs0 += p0 + p1;
            rs1 += p2 + p3;
        }
        rs0 += __shfl_xor_sync(0xffffffffu, rs0, 1);
        rs0 += __shfl_xor_sync(0xffffffffu, rs0, 2);
        rs1 += __shfl_xor_sync(0xffffffffu, rs1, 1);
        rs1 += __shfl_xor_sync(0xffffffffu, rs1, 2);
        l0 = l0 * corr0 + rs0;
        l1 = l1 * corr1 + rs1;
        #pragma unroll
        for (int nd = 0; nd < 8; nd++) {
            O[nd][0] *= corr0; O[nd][1] *= corr0;
            O[nd][2] *= corr1; O[nd][3] *= corr1;
        }

        #pragma unroll
        for (int kt = 0; kt < 8; kt++) {
            uint32_t a[4];
            a[0] = pack_h(S[2 * kt][0],     S[2 * kt][1]);
            a[1] = pack_h(S[2 * kt][2],     S[2 * kt][3]);
            a[2] = pack_h(S[2 * kt + 1][0], S[2 * kt + 1][1]);
            a[3] = pack_h(S[2 * kt + 1][2], S[2 * kt + 1][3]);
            #pragma unroll
            for (int nd = 0; nd < 4; nd++) {
                uint32_t off = ((uint32_t)(nd * 16 + rowB) * PADV + kt * 16 + koB) * 2;
                uint32_t vh[4], vl[4];
                ldsm4(b + KT_B + off, vh);
                ldsm4(b + KT_B + VT_B + off, vl);
                mma16816h(O[2 * nd],     a, vh[0], vh[1]);
                mma16816h(O[2 * nd],     a, vl[0], vl[1]);
                mma16816h(O[2 * nd + 1], a, vh[2], vh[3]);
                mma16816h(O[2 * nd + 1], a, vl[2], vl[3]);
            }
        }
        __syncthreads();
    }

    float inv0 = 1.f / l0, inv1 = 1.f / l1;
    #pragma unroll
    for (int nd = 0; nd < 8; nd++) {
        int d = h * HDIM + nd * 8 + c2;
        *(float2*)&Y[(size_t)row0 * DMODEL + d] = make_float2(O[nd][0] * inv0, O[nd][1] * inv0);
        *(float2*)&Y[(size_t)row1 * DMODEL + d] = make_float2(O[nd][2] * inv1, O[nd][3] * inv1);
    }
}

// ---------------- launch ----------------
extern "C" void kernel_launch(void* const* d_in, const int* in_sizes, int n_in,
                              void* d_out, int out_size) {
    const float* x      = (const float*)d_in[0];
    const float* w_qkv  = (const float*)d_in[1];
    const float* w_proj = (const float*)d_in[2];
    float* out = (float*)d_out;
    (void)in_sizes; (void)n_in; (void)out_size;

    float *p_v, *p_y;
    __half *p_xh, *p_xl, *p_yh, *p_yl, *p_wq, *p_wp;
    __half *p_qfh, *p_qfl, *p_kf, *p_vfh, *p_vfl;
    cudaGetSymbolAddress((void**)&p_v,  g_v);
    cudaGetSymbolAddress((void**)&p_y,  g_y);
    cudaGetSymbolAddress((void**)&p_xh, g_xh);
    cudaGetSymbolAddress((void**)&p_xl, g_xl);
    cudaGetSymbolAddress((void**)&p_yh, g_yh);
    cudaGetSymbolAddress((void**)&p_yl, g_yl);
    cudaGetSymbolAddress((void**)&p_wq, g_wq);
    cudaGetSymbolAddress((void**)&p_wp, g_wp);
    cudaGetSymbolAddress((void**)&p_qfh, g_qfh);
    cudaGetSymbolAddress((void**)&p_qfl, g_qfl);
    cudaGetSymbolAddress((void**)&p_kf,  g_kf);
    cudaGetSymbolAddress((void**)&p_vfh, g_vfh);
    cudaGetSymbolAddress((void**)&p_vfl, g_vfl);

    cudaFuncSetAttribute(gemm_mma_kernel, cudaFuncAttributeMaxDynamicSharedMemorySize, GEMM_SMEM);
    cudaFuncSetAttribute(attn_mma_kernel, cudaFuncAttributeMaxDynamicSharedMemorySize, ATTN_SMEM);

    // 1. RoPE tables (needed by QKV epilogue)
    rope_table_kernel<<<(SEQ * HALF + 255) / 256, 256>>>();

    // 2. prep: x split (fp16), w_qkv transpose (fp16 single)
    split_half_kernel<<<(SEQ * DMODEL + 255) / 256, 256>>>(x, p_xh, p_xl, SEQ * DMODEL);
    {
        dim3 grid(3 * DMODEL / 32, DMODEL / 32);
        transpose_half_kernel<<<grid, dim3(32, 8)>>>(w_qkv, p_wq, DMODEL, 3 * DMODEL);
    }

    // 3. QKV projection with fused RoPE epilogue -> qfh/qfl, kf (fp16), v (fp32)
    {
        dim3 grid(3 * DMODEL / 128, SEQ / 128);
        gemm_mma_kernel<<<grid, 256, GEMM_SMEM>>>(p_xh, p_xl, p_wq,
                                                  nullptr, p_qfh, p_qfl, p_kf, p_v,
                                                  3 * DMODEL, DMODEL, 1);
    }

    // 4. V transpose + split
    {
        dim3 grid(SEQ / 64, NHEAD);
        vsplit_kernel<<<grid, 256>>>();
    }

    // 5. flash attention on tensor cores
    {
        dim3 grid(SEQ / 128, NHEAD);
        attn_mma_kernel<<<grid, 256, ATTN_SMEM>>>(p_qfh, p_qfl, p_kf, p_vfh, p_vfl, p_y);
    }

    // 6. output projection
    split_half_kernel<<<(SEQ * DMODEL + 255) / 256, 256>>>(p_y, p_yh, p_yl, SEQ * DMODEL);
    {
        dim3 grid(DMODEL / 32, DMODEL / 32);
        transpose_half_kernel<<<grid, dim3(32, 8)>>>(w_proj, p_wp, DMODEL, DMODEL);
    }
    {
        dim3 grid(DMODEL / 128, SEQ / 128);
        gemm_mma_kernel<<<grid, 256, GEMM_SMEM>>>(p_yh, p_yl, p_wp,
                                                  out, nullptr, nullptr, nullptr, nullptr,
                                                  DMODEL, DMODEL, 0);
    }
}

// round 11
// speedup vs baseline: 6.0810x; 1.0330x over previous
#include <cuda_runtime.h>
#include <cuda_bf16.h>
#include <cuda_fp16.h>
#include <math.h>
#include <stdint.h>

// Problem constants
#define SEQ    4096
#define DMODEL 1024
#define NHEAD  16
#define HDIM   64
#define HALF   32   // HDIM/2

// ---------------- scratch (device globals) ----------------
__device__ float g_v[(size_t)NHEAD * SEQ * HDIM];   // [h][t][d] fp32
__device__ float g_cos[SEQ * HALF];
__device__ float g_sin[SEQ * HALF];

// fp16 split operands for projections
__device__ __half g_xh[(size_t)SEQ * DMODEL];
__device__ __half g_xl[(size_t)SEQ * DMODEL];
__device__ __half g_yh[(size_t)SEQ * DMODEL];      // attention output hi (written fused)
__device__ __half g_yl[(size_t)SEQ * DMODEL];      //                  lo
__device__ __half g_wq[(size_t)3 * DMODEL * DMODEL];  // w_qkv^T [3072][1024] fp16
__device__ __half g_wp[(size_t)DMODEL * DMODEL];      // w_proj^T [1024][1024] fp16

// fp16 operands for attention (RoPE'd; q pre-scaled by 1/8, split-2; k single; v^T single)
__device__ __half g_qfh[(size_t)NHEAD * SEQ * HDIM];   // [h][t][d] hi
__device__ __half g_qfl[(size_t)NHEAD * SEQ * HDIM];   //            lo
__device__ __half g_kf [(size_t)NHEAD * SEQ * HDIM];   // [h][t][d] single
__device__ __half g_vfh[(size_t)NHEAD * HDIM * SEQ];   // [h][d][t] single (V^T)

// ---------------- helpers ----------------
__device__ __forceinline__ uint32_t smem_to_u32(const void* p) {
    uint32_t a;
    asm("{ .reg .u64 t; cvta.to.shared.u64 t, %1; cvt.u32.u64 %0, t; }" : "=r"(a) : "l"(p));
    return a;
}
__device__ __forceinline__ void ldsm4(uint32_t addr, uint32_t r[4]) {
    asm volatile("ldmatrix.sync.aligned.m8n8.x4.shared.b16 {%0,%1,%2,%3}, [%4];"
                 : "=r"(r[0]), "=r"(r[1]), "=r"(r[2]), "=r"(r[3]) : "r"(addr));
}
__device__ __forceinline__ void mma16816h(float c[4], const uint32_t a[4], uint32_t b0, uint32_t b1) {
    asm volatile("mma.sync.aligned.m16n8k16.row.col.f32.f16.f16.f32 "
                 "{%0,%1,%2,%3}, {%4,%5,%6,%7}, {%8,%9}, {%0,%1,%2,%3};"
                 : "+f"(c[0]), "+f"(c[1]), "+f"(c[2]), "+f"(c[3])
                 : "r"(a[0]), "r"(a[1]), "r"(a[2]), "r"(a[3]), "r"(b0), "r"(b1));
}
#define CP16(dst, src) \
    asm volatile("cp.async.ca.shared.global [%0], [%1], 16;" :: "r"(dst), "l"(__cvta_generic_to_global(src)))
#define CP_COMMIT() asm volatile("cp.async.commit_group;")
#define CP_WAIT(N)  asm volatile("cp.async.wait_group %0;" :: "n"(N))

__device__ __forceinline__ uint32_t pack_h(float a, float b) {
    __half2 h = __floats2half2_rn(a, b);
    return *(uint32_t*)&h;
}

// ---------------- RoPE cos/sin table ----------------
__global__ void rope_table_kernel() {
    int idx = blockIdx.x * blockDim.x + threadIdx.x;
    if (idx >= SEQ * HALF) return;
    int d = idx & (HALF - 1);
    int t = idx >> 5;
    double inv = exp(-log(10000.0) * (double)d / (double)HALF);
    float invf = (float)inv;
    float f = (float)t * invf;
    g_cos[idx] = (float)cos((double)f);
    g_sin[idx] = (float)sin((double)f);
}

// ---------------- fp32 -> fp16 hi/lo split ----------------
__global__ void split_half_kernel(const float* __restrict__ src, __half* __restrict__ hi,
                                  __half* __restrict__ lo, int n) {
    int i = blockIdx.x * blockDim.x + threadIdx.x;
    if (i >= n) return;
    float v = src[i];
    __half h = __float2half_rn(v);
    hi[i] = h;
    lo[i] = __float2half_rn(v - __half2float(h));
}

// ---------------- transpose + fp16: W[K][N] -> Wt [N][K] ----------------
__global__ void transpose_half_kernel(const float* __restrict__ W,
                                      __half* __restrict__ T, int K, int N) {
    __shared__ float t[32][33];
    int n0 = blockIdx.x * 32, k0 = blockIdx.y * 32;
    int tx = threadIdx.x, ty = threadIdx.y;
    #pragma unroll
    for (int r = 0; r < 4; r++)
        t[ty + 8 * r][tx] = W[(size_t)(k0 + ty + 8 * r) * N + n0 + tx];
    __syncthreads();
    #pragma unroll
    for (int r = 0; r < 4; r++)
        T[(size_t)(n0 + ty + 8 * r) * K + k0 + tx] = __float2half_rn(t[tx][ty + 8 * r]);
}

// ---------------- V transpose: g_v [h][t][d] -> vfh [h][d][t] (fp16 single) ----------------
__global__ __launch_bounds__(256) void vsplit_kernel() {
    __shared__ float vs[64][65];
    const int h = blockIdx.y, t0 = blockIdx.x * 64;
    const int tid = threadIdx.x;
    const size_t base_ht = ((size_t)h * SEQ + t0) * HDIM;
    #pragma unroll
    for (int i = 0; i < 16; i++) {
        int idx = tid + i * 256;
        int tl = idx >> 6, d = idx & 63;
        vs[tl][d] = g_v[base_ht + (size_t)tl * HDIM + d];
    }
    __syncthreads();
    #pragma unroll
    for (int i = 0; i < 16; i++) {
        int idx = tid + i * 256;
        int d = idx >> 6, tl = idx & 63;
        g_vfh[((size_t)h * HDIM + d) * SEQ + t0 + tl] = __float2half_rn(vs[tl][d]);
    }
}

// ---------------- mma.sync fp16 split-2 GEMM, cp.async 3-stage ----------------
// C = A @ B; A fp16 hi/lo [M][K]; B fp16 single, transposed [N][K].
// CTA 128x128, BK=32, 8 warps, warp tile 32x64.
// mode 1: fused RoPE epilogue -> q/k fp16 (+split) and v fp32.  mode 0: fp32 C.
#define BKC 32
#define TS 40
#define TILE_ELEMS (128 * TS)
#define TILE_BYTES (TILE_ELEMS * 2)
#define GEMM_SMEM (9 * TILE_BYTES)     // 3 stages x 3 tiles = 92160 B

__global__ __launch_bounds__(256, 1) void gemm_mma_kernel(
    const __half* __restrict__ Ah, const __half* __restrict__ Al,
    const __half* __restrict__ B,
    float* __restrict__ C, __half* __restrict__ Qh, __half* __restrict__ Ql,
    __half* __restrict__ Kf, float* __restrict__ V, int N, int K, int mode)
{
    extern __shared__ __half sm_g[];
    const int tid = threadIdx.x;
    const int wid = tid >> 5, lid = tid & 31;
    const int brow = blockIdx.y * 128, bcol = blockIdx.x * 128;
    const int wm = wid >> 1, wn = wid & 1;
    const uint32_t smem_base = smem_to_u32(sm_g);

    const __half* srcs[3] = { Ah, Al, B };

    float acc[2][8][4];
    #pragma unroll
    for (int mi = 0; mi < 2; mi++)
        #pragma unroll
        for (int ni = 0; ni < 8; ni++)
            #pragma unroll
            for (int r = 0; r < 4; r++) acc[mi][ni][r] = 0.f;

    const int rowA = lid & 15;
    const int koA  = (lid >> 4) << 3;
    const int rowB = (lid & 7) + ((lid >> 4) << 3);
    const int koB  = ((lid >> 3) & 1) << 3;

    const int ld_row = tid >> 2, ld_g = tid & 3;   // per-thread cp.async slot

    auto issueg = [&](int c) {
        const int st = c % 3;
        const uint32_t base = smem_base + (uint32_t)st * 3 * TILE_BYTES;
        #pragma unroll
        for (int t = 0; t < 3; t++) {
            const __half* s = srcs[t];
            const int rb = (t < 2) ? brow : bcol;
            const uint32_t tb = base + (uint32_t)t * TILE_BYTES;
            #pragma unroll
            for (int j = 0; j < 2; j++) {
                int row = ld_row + j * 64;
                CP16(tb + (uint32_t)(row * TS + ld_g * 8) * 2,
                     s + (size_t)(rb + row) * K + c * BKC + ld_g * 8);
            }
        }
        CP_COMMIT();
    };
    auto compute = [&](int st) {
        const uint32_t bA_h = smem_base + (uint32_t)(st * 3 + 0) * TILE_BYTES;
        const uint32_t bA_l = smem_base + (uint32_t)(st * 3 + 1) * TILE_BYTES;
        const uint32_t bB   = smem_base + (uint32_t)(st * 3 + 2) * TILE_BYTES;
        #pragma unroll
        for (int ks = 0; ks < 2; ks++) {
            uint32_t ah[2][4], al[2][4];
            #pragma unroll
            for (int mi = 0; mi < 2; mi++) {
                uint32_t off = ((uint32_t)(wm * 32 + mi * 16 + rowA) * TS + ks * 16 + koA) * 2;
                ldsm4(bA_h + off, ah[mi]);
                ldsm4(bA_l + off, al[mi]);
            }
            #pragma unroll
            for (int ni2 = 0; ni2 < 4; ni2++) {
                uint32_t off = ((uint32_t)(wn * 64 + ni2 * 16 + rowB) * TS + ks * 16 + koB) * 2;
                uint32_t bh[4];
                ldsm4(bB + off, bh);
                #pragma unroll
                for (int half2i = 0; half2i < 2; half2i++) {
                    const int ni = ni2 * 2 + half2i;
                    const uint32_t b0 = bh[half2i * 2], b1 = bh[half2i * 2 + 1];
                    #pragma unroll
                    for (int mi = 0; mi < 2; mi++) {
                        mma16816h(acc[mi][ni], ah[mi], b0, b1);
                        mma16816h(acc[mi][ni], al[mi], b0, b1);
                    }
                }
            }
        }
    };

    const int nc = K / BKC;
    issueg(0);
    issueg(1);
    for (int c = 0; c < nc; c++) {
        if (c == nc - 1) { CP_WAIT(0); } else { CP_WAIT(1); }
        __syncthreads();
        if (c + 2 < nc) issueg(c + 2);
        compute(c % 3);
    }

    const int gr = lid >> 2, c2v = (lid & 3) * 2;
    if (mode == 1) {
        // fused RoPE + fp16 split epilogue (warp tile = one head).
        #pragma unroll
        for (int mi = 0; mi < 2; mi++) {
            int row0 = brow + wm * 32 + mi * 16 + gr;
            int row1 = row0 + 8;
            #pragma unroll
            for (int ni = 0; ni < 4; ni++) {
                int col = bcol + wn * 64 + ni * 8 + c2v;
                int sect = col >> 10;
                int nn = col & 1023;
                int h = nn >> 6, d = nn & 63;      // d < 32
                float* a0 = acc[mi][ni];
                float* a1 = acc[mi][ni + 4];
                size_t b0 = ((size_t)h * SEQ + row0) * HDIM;
                size_t b1 = ((size_t)h * SEQ + row1) * HDIM;
                if (sect == 2) {
                    *(float2*)&V[b0 + d]      = make_float2(a0[0], a0[1]);
                    *(float2*)&V[b1 + d]      = make_float2(a0[2], a0[3]);
                    *(float2*)&V[b0 + d + 32] = make_float2(a1[0], a1[1]);
                    *(float2*)&V[b1 + d + 32] = make_float2(a1[2], a1[3]);
                } else {
                    float2 c0 = *(const float2*)&g_cos[row0 * HALF + d];
                    float2 s0 = *(const float2*)&g_sin[row0 * HALF + d];
                    float2 c1 = *(const float2*)&g_cos[row1 * HALF + d];
                    float2 s1 = *(const float2*)&g_sin[row1 * HALF + d];
                    float e1[4], e2[4];
                    e1[0] = a0[0] * c0.x - a1[0] * s0.x;  e2[0] = a1[0] * c0.x + a0[0] * s0.x;
                    e1[1] = a0[1] * c0.y - a1[1] * s0.y;  e2[1] = a1[1] * c0.y + a0[1] * s0.y;
                    e1[2] = a0[2] * c1.x - a1[2] * s1.x;  e2[2] = a1[2] * c1.x + a0[2] * s1.x;
                    e1[3] = a0[3] * c1.y - a1[3] * s1.y;  e2[3] = a1[3] * c1.y + a0[3] * s1.y;
                    if (sect == 0) {
                        #pragma unroll
                        for (int r = 0; r < 4; r++) { e1[r] *= 0.125f; e2[r] *= 0.125f; }
                        __half2 h10 = __floats2half2_rn(e1[0], e1[1]);
                        __half2 h12 = __floats2half2_rn(e1[2], e1[3]);
                        __half2 h20 = __floats2half2_rn(e2[0], e2[1]);
                        __half2 h22 = __floats2half2_rn(e2[2], e2[3]);
                        *(__half2*)&Qh[b0 + d]      = h10;
                        *(__half2*)&Qh[b1 + d]      = h12;
                        *(__half2*)&Qh[b0 + d + 32] = h20;
                        *(__half2*)&Qh[b1 + d + 32] = h22;
                        *(__half2*)&Ql[b0 + d] =
                            __floats2half2_rn(e1[0] - __low2float(h10), e1[1] - __high2float(h10));
                        *(__half2*)&Ql[b1 + d] =
                            __floats2half2_rn(e1[2] - __low2float(h12), e1[3] - __high2float(h12));
                        *(__half2*)&Ql[b0 + d + 32] =
                            __floats2half2_rn(e2[0] - __low2float(h20), e2[1] - __high2float(h20));
                        *(__half2*)&Ql[b1 + d + 32] =
                            __floats2half2_rn(e2[2] - __low2float(h22), e2[3] - __high2float(h22));
                    } else {
                        *(__half2*)&Kf[b0 + d]      = __floats2half2_rn(e1[0], e1[1]);
                        *(__half2*)&Kf[b1 + d]      = __floats2half2_rn(e1[2], e1[3]);
                        *(__half2*)&Kf[b0 + d + 32] = __floats2half2_rn(e2[0], e2[1]);
                        *(__half2*)&Kf[b1 + d + 32] = __floats2half2_rn(e2[2], e2[3]);
                    }
                }
            }
        }
    } else {
        #pragma unroll
        for (int mi = 0; mi < 2; mi++) {
            #pragma unroll
            for (int ni = 0; ni < 8; ni++) {
                int row0 = brow + wm * 32 + mi * 16 + gr;
                int col  = bcol + wn * 64 + ni * 8 + c2v;
                *(float2*)&C[(size_t)row0 * N + col] =
                    make_float2(acc[mi][ni][0], acc[mi][ni][1]);
                *(float2*)&C[(size_t)(row0 + 8) * N + col] =
                    make_float2(acc[mi][ni][2], acc[mi][ni][3]);
            }
        }
    }
}

// ---------------- Flash attention via mma.sync (Q split-2, K/P/V single, causal) ----------------
#define PADK 72
#define PADV 136
#define KT_B (128 * PADK * 2)           // 18432 B
#define VT_B (64 * PADV * 2)            // 17408 B
#define BUF_B (KT_B + VT_B)             // 35840 B
// Steady state uses 2*BUF_B = 71680; the Q-tile staging transiently needs
// BUF_B + 2*KT_B = 72704 (round-10 overflow bug). Allocate the max.
#define ATTN_SMEM (BUF_B + 2 * KT_B)    // 72704 B

__global__ __launch_bounds__(256, 1) void attn_mma_kernel(
    const __half* __restrict__ Qfh, const __half* __restrict__ Qfl,
    const __half* __restrict__ Kf,
    const __half* __restrict__ Vfh,
    __half* __restrict__ Yh, __half* __restrict__ Yl)
{
    extern __shared__ char asmem[];
    const uint32_t sb = smem_to_u32(asmem);
    const int tid = threadIdx.x;
    const int wid = tid >> 5, lid = tid & 31;
    const int h = blockIdx.y;
    const int qt = gridDim.x - 1 - blockIdx.x;      // longest-first
    const int q0 = qt * 128;

    const __half* pQh = Qfh + (size_t)h * SEQ * HDIM;
    const __half* pQl = Qfl + (size_t)h * SEQ * HDIM;
    const __half* pK  = Kf  + (size_t)h * SEQ * HDIM;
    const __half* pVh = Vfh + (size_t)h * HDIM * SEQ;

    #pragma unroll
    for (int i = 0; i < 4; i++) {
        int idx = tid + i * 256;
        int row = idx >> 3, g = idx & 7;
        *(float4*)(asmem + BUF_B + row * (PADK * 2) + g * 16) =
            *(const float4*)(pQh + (size_t)(q0 + row) * HDIM + g * 8);
        *(float4*)(asmem + BUF_B + KT_B + row * (PADK * 2) + g * 16) =
            *(const float4*)(pQl + (size_t)(q0 + row) * HDIM + g * 8);
    }
    __syncthreads();

    const int rowA = lid & 15;
    const int koA  = (lid >> 4) << 3;
    const int rowB = (lid & 7) + ((lid >> 4) << 3);
    const int koB  = ((lid >> 3) & 1) << 3;

    uint32_t qfh[4][4], qfl[4][4];
    #pragma unroll
    for (int ks = 0; ks < 4; ks++) {
        uint32_t off = ((uint32_t)(wid * 16 + rowA) * PADK + ks * 16 + koA) * 2;
        ldsm4(sb + BUF_B + off, qfh[ks]);
        ldsm4(sb + BUF_B + KT_B + off, qfl[ks]);
    }
    __syncthreads();

    float S[16][4], O[8][4];
    float m0 = -1e30f, m1 = -1e30f, l0 = 0.f, l1 = 0.f;
    #pragma unroll
    for (int i = 0; i < 8; i++)
        #pragma unroll
        for (int r = 0; r < 4; r++) O[i][r] = 0.f;

    auto issue = [&](int j) {
        uint32_t b = sb + (uint32_t)(j & 1) * BUF_B;
        int k0 = j * 128;
        #pragma unroll
        for (int i = 0; i < 4; i++) {
            int idx = tid + i * 256;
            int row = idx >> 3, g = idx & 7;
            CP16(b + (uint32_t)(row * (PADK * 2) + g * 16),
                 pK + (size_t)(k0 + row) * HDIM + g * 8);
        }
        #pragma unroll
        for (int i = 0; i < 4; i++) {
            int idx = tid + i * 256;
            int row = idx >> 4, g = idx & 15;
            CP16(b + KT_B + (uint32_t)(row * (PADV * 2) + g * 16),
                 pVh + (size_t)row * SEQ + k0 + g * 8);
        }
        CP_COMMIT();
    };

    const int gr = lid >> 2, c2 = (lid & 3) * 2;
    const int row0 = q0 + wid * 16 + gr;
    const int row1 = row0 + 8;

    issue(0);
    for (int j = 0; j <= qt; j++) {
        if (j < qt) { issue(j + 1); CP_WAIT(1); }
        else        { CP_WAIT(0); }
        __syncthreads();
        const uint32_t b = sb + (uint32_t)(j & 1) * BUF_B;

        #pragma unroll
        for (int ni = 0; ni < 16; ni++)
            #pragma unroll
            for (int r = 0; r < 4; r++) S[ni][r] = 0.f;

        #pragma unroll
        for (int nt = 0; nt < 8; nt++) {
            #pragma unroll
            for (int ks = 0; ks < 4; ks++) {
                uint32_t off = ((uint32_t)(nt * 16 + rowB) * PADK + ks * 16 + koB) * 2;
                uint32_t bh[4];
                ldsm4(b + off, bh);
                mma16816h(S[2 * nt],     qfh[ks], bh[0], bh[1]);
                mma16816h(S[2 * nt],     qfl[ks], bh[0], bh[1]);
                mma16816h(S[2 * nt + 1], qfh[ks], bh[2], bh[3]);
                mma16816h(S[2 * nt + 1], qfl[ks], bh[2], bh[3]);
            }
        }

        if (j == qt) {
            #pragma unroll
            for (int ni = 0; ni < 16; ni++) {
                int kc = j * 128 + ni * 8 + c2;
                if (kc     > row0) S[ni][0] = -1e30f;
                if (kc + 1 > row0) S[ni][1] = -1e30f;
                if (kc     > row1) S[ni][2] = -1e30f;
                if (kc + 1 > row1) S[ni][3] = -1e30f;
            }
        }

        float mx0 = -1e30f, mx1 = -1e30f;
        #pragma unroll
        for (int ni = 0; ni < 16; ni++) {
            mx0 = fmaxf(mx0, fmaxf(S[ni][0], S[ni][1]));
            mx1 = fmaxf(mx1, fmaxf(S[ni][2], S[ni][3]));
        }
        mx0 = fmaxf(mx0, __shfl_xor_sync(0xffffffffu, mx0, 1));
        mx0 = fmaxf(mx0, __shfl_xor_sync(0xffffffffu, mx0, 2));
        mx1 = fmaxf(mx1, __shfl_xor_sync(0xffffffffu, mx1, 1));
        mx1 = fmaxf(mx1, __shfl_xor_sync(0xffffffffu, mx1, 2));
        float mn0 = fmaxf(m0, mx0), mn1 = fmaxf(m1, mx1);
        float corr0 = __expf(m0 - mn0), corr1 = __expf(m1 - mn1);
        m0 = mn0; m1 = mn1;

        float rs0 = 0.f, rs1 = 0.f;
        #pragma unroll
        for (int ni = 0; ni < 16; ni++) {
            float p0 = __expf(S[ni][0] - mn0);
            float p1 = __expf(S[ni][1] - mn0);
            float p2 = __expf(S[ni][2] - mn1);
            float p3 = __expf(S[ni][3] - mn1);
            S[ni][0] = p0; S[ni][1] = p1; S[ni][2] = p2; S[ni][3] = p3;
            rs0 += p0 + p1;
            rs1 += p2 + p3;
        }
        rs0 += __shfl_xor_sync(0xffffffffu, rs0, 1);
        rs0 += __shfl_xor_sync(0xffffffffu, rs0, 2);
        rs1 += __shfl_xor_sync(0xffffffffu, rs1, 1);
        rs1 += __shfl_xor_sync(0xffffffffu, rs1, 2);
        l0 = l0 * corr0 + rs0;
        l1 = l1 * corr1 + rs1;
        #pragma unroll
        for (int nd = 0; nd < 8; nd++) {
            O[nd][0] *= corr0; O[nd][1] *= corr0;
            O[nd][2] *= corr1; O[nd][3] *= corr1;
        }

        #pragma unroll
        for (int kt = 0; kt < 8; kt++) {
            uint32_t a[4];
            a[0] = pack_h(S[2 * kt][0],     S[2 * kt][1]);
            a[1] = pack_h(S[2 * kt][2],     S[2 * kt][3]);
            a[2] = pack_h(S[2 * kt + 1][0], S[2 * kt + 1][1]);
            a[3] = pack_h(S[2 * kt + 1][2], S[2 * kt + 1][3]);
            #pragma unroll
            for (int nd = 0; nd < 4; nd++) {
                uint32_t off = ((uint32_t)(nd * 16 + rowB) * PADV + kt * 16 + koB) * 2;
                uint32_t vh[4];
                ldsm4(b + KT_B + off, vh);
                mma16816h(O[2 * nd],     a, vh[0], vh[1]);
                mma16816h(O[2 * nd + 1], a, vh[2], vh[3]);
            }
        }
        __syncthreads();
    }

    // ---- epilogue: fused fp16 hi/lo split write ----
    float inv0 = 1.f / l0, inv1 = 1.f / l1;
    #pragma unroll
    for (int nd = 0; nd < 8; nd++) {
        int d = h * HDIM + nd * 8 + c2;
        float o00 = O[nd][0] * inv0, o01 = O[nd][1] * inv0;
        float o10 = O[nd][2] * inv1, o11 = O[nd][3] * inv1;
        __half2 h0 = __floats2half2_rn(o00, o01);
        __half2 h1 = __floats2half2_rn(o10, o11);
        *(__half2*)&Yh[(size_t)row0 * DMODEL + d] = h0;
        *(__half2*)&Yh[(size_t)row1 * DMODEL + d] = h1;
        *(__half2*)&Yl[(size_t)row0 * DMODEL + d] =
            __floats2half2_rn(o00 - __low2float(h0), o01 - __high2float(h0));
        *(__half2*)&Yl[(size_t)row1 * DMODEL + d] =
            __floats2half2_rn(o10 - __low2float(h1), o11 - __high2float(h1));
    }
}

// ---------------- launch ----------------
extern "C" void kernel_launch(void* const* d_in, const int* in_sizes, int n_in,
                              void* d_out, int out_size) {
    const float* x      = (const float*)d_in[0];
    const float* w_qkv  = (const float*)d_in[1];
    const float* w_proj = (const float*)d_in[2];
    float* out = (float*)d_out;
    (void)in_sizes; (void)n_in; (void)out_size;

    float *p_v;
    __half *p_xh, *p_xl, *p_yh, *p_yl, *p_wq, *p_wp;
    __half *p_qfh, *p_qfl, *p_kf, *p_vfh;
    cudaGetSymbolAddress((void**)&p_v,  g_v);
    cudaGetSymbolAddress((void**)&p_xh, g_xh);
    cudaGetSymbolAddress((void**)&p_xl, g_xl);
    cudaGetSymbolAddress((void**)&p_yh, g_yh);
    cudaGetSymbolAddress((void**)&p_yl, g_yl);
    cudaGetSymbolAddress((void**)&p_wq, g_wq);
    cudaGetSymbolAddress((void**)&p_wp, g_wp);
    cudaGetSymbolAddress((void**)&p_qfh, g_qfh);
    cudaGetSymbolAddress((void**)&p_qfl, g_qfl);
    cudaGetSymbolAddress((void**)&p_kf,  g_kf);
    cudaGetSymbolAddress((void**)&p_vfh, g_vfh);

    cudaFuncSetAttribute(gemm_mma_kernel, cudaFuncAttributeMaxDynamicSharedMemorySize, GEMM_SMEM);
    cudaFuncSetAttribute(attn_mma_kernel, cudaFuncAttributeMaxDynamicSharedMemorySize, ATTN_SMEM);

    // 1. RoPE tables (needed by QKV epilogue)
    rope_table_kernel<<<(SEQ * HALF + 255) / 256, 256>>>();

    // 2. prep: x split (fp16), w_qkv transpose (fp16 single)
    split_half_kernel<<<(SEQ * DMODEL + 255) / 256, 256>>>(x, p_xh, p_xl, SEQ * DMODEL);
    {
        dim3 grid(3 * DMODEL / 32, DMODEL / 32);
        transpose_half_kernel<<<grid, dim3(32, 8)>>>(w_qkv, p_wq, DMODEL, 3 * DMODEL);
    }

    // 3. QKV projection with fused RoPE epilogue -> qfh/qfl, kf (fp16), v (fp32)
    {
        dim3 grid(3 * DMODEL / 128, SEQ / 128);
        gemm_mma_kernel<<<grid, 256, GEMM_SMEM>>>(p_xh, p_xl, p_wq,
                                                  nullptr, p_qfh, p_qfl, p_kf, p_v,
                                                  3 * DMODEL, DMODEL, 1);
    }

    // 4. V transpose (fp16 single)
    {
        dim3 grid(SEQ / 64, NHEAD);
        vsplit_kernel<<<grid, 256>>>();
    }

    // 5. flash attention on tensor cores; writes yh/yl fp16 split directly
    {
        dim3 grid(SEQ / 128, NHEAD);
        attn_mma_kernel<<<grid, 256, ATTN_SMEM>>>(p_qfh, p_qfl, p_kf, p_vfh, p_yh, p_yl);
    }

    // 6. output projection (w_proj transpose prepped here; independent of attention)
    {
        dim3 grid(DMODEL / 32, DMODEL / 32);
        transpose_half_kernel<<<grid, dim3(32, 8)>>>(w_proj, p_wp, DMODEL, DMODEL);
    }
    {
        dim3 grid(DMODEL / 128, SEQ / 128);
        gemm_mma_kernel<<<grid, 256, GEMM_SMEM>>>(p_yh, p_yl, p_wp,
                                                  out, nullptr, nullptr, nullptr, nullptr,
                                                  DMODEL, DMODEL, 0);
    }
}